// round 1
// baseline (speedup 1.0000x reference)
#include <cuda_runtime.h>
#include <cuda_bf16.h>
#include <math.h>

// Problem constants (fixed by the dataset)
#define NN   50000      // nodes
#define EE   800000     // edges
#define IND  256        // input dim
#define HH   4          // heads
#define FF   64         // out feats / head
#define HF   256        // H*F
#define EFD  64         // edge feat dim
#define NT   8          // num etypes
#define SLOPE 0.2f

// ---------------- scratch (device globals; no allocation allowed) -------------
__device__ float g_feat[NN * HF];      // projected node features
__device__ float g_el[NN * HH];
__device__ float g_er[NN * HH];
__device__ float g_ee[NT * HH];
__device__ int   g_cnt[NN + 1];
__device__ int   g_off[NN + 1];
__device__ int   g_cursor[NN];
__device__ int   g_eids[EE];
__device__ int   g_bsum[64];
__device__ int   g_bpre[65];

// ---------------- GEMM: feat = nfeat @ fc_w  (M=50000, N=256, K=256) ----------
#define BM 128
#define BN 128
#define BK 16
#define TM 8
#define TN 8

__global__ void __launch_bounds__(256, 2)
sgemm_kernel(const float* __restrict__ A, const float* __restrict__ B,
             float* __restrict__ C, int M)
{
    __shared__ float As[BK][BM];   // transposed A tile
    __shared__ float Bs[BK][BN];

    const int t  = threadIdx.x;          // 0..255
    const int tx = t & 15;               // col group
    const int ty = t >> 4;               // row group
    const int m0 = blockIdx.x * BM;
    const int n0 = blockIdx.y * BN;

    float acc[TM][TN];
#pragma unroll
    for (int i = 0; i < TM; i++)
#pragma unroll
        for (int j = 0; j < TN; j++) acc[i][j] = 0.f;

    // A load mapping: thread t loads 8 floats = linear [t*8, t*8+8) of the 128x16 tile
    const int a_row = t >> 1;
    const int a_col = (t & 1) * 8;
    // B load mapping: thread t loads 8 floats: row t/16 (0..15), col (t%16)*8
    const int b_row = t >> 4;
    const int b_col = (t & 15) * 8;

    for (int k0 = 0; k0 < IND; k0 += BK) {
        // load A tile (guarded rows), store transposed
        {
            int gr = m0 + a_row;
            float4 v0, v1;
            if (gr < M) {
                const float* p = A + (size_t)gr * IND + k0 + a_col;
                v0 = *(const float4*)p;
                v1 = *(const float4*)(p + 4);
            } else {
                v0 = make_float4(0, 0, 0, 0);
                v1 = v0;
            }
            As[a_col + 0][a_row] = v0.x;
            As[a_col + 1][a_row] = v0.y;
            As[a_col + 2][a_row] = v0.z;
            As[a_col + 3][a_row] = v0.w;
            As[a_col + 4][a_row] = v1.x;
            As[a_col + 5][a_row] = v1.y;
            As[a_col + 6][a_row] = v1.z;
            As[a_col + 7][a_row] = v1.w;
        }
        // load B tile
        {
            const float* p = B + (size_t)(k0 + b_row) * HF + n0 + b_col;
            float4 v0 = *(const float4*)p;
            float4 v1 = *(const float4*)(p + 4);
            *(float4*)&Bs[b_row][b_col]     = v0;
            *(float4*)&Bs[b_row][b_col + 4] = v1;
        }
        __syncthreads();

#pragma unroll
        for (int k = 0; k < BK; k++) {
            float a[TM], b[TN];
#pragma unroll
            for (int i = 0; i < TM; i++) a[i] = As[k][ty * TM + i];
#pragma unroll
            for (int j = 0; j < TN; j++) b[j] = Bs[k][tx * TN + j];
#pragma unroll
            for (int i = 0; i < TM; i++)
#pragma unroll
                for (int j = 0; j < TN; j++) acc[i][j] += a[i] * b[j];
        }
        __syncthreads();
    }

    // store
#pragma unroll
    for (int i = 0; i < TM; i++) {
        int gr = m0 + ty * TM + i;
        if (gr < M) {
            float* p = C + (size_t)gr * HF + n0 + tx * TN;
            *(float4*)p       = make_float4(acc[i][0], acc[i][1], acc[i][2], acc[i][3]);
            *(float4*)(p + 4) = make_float4(acc[i][4], acc[i][5], acc[i][6], acc[i][7]);
        }
    }
}

// ---------------- el / er per node -------------------------------------------
__global__ void elr_kernel(const float* __restrict__ attn_l,
                           const float* __restrict__ attn_r)
{
    const int n = blockIdx.x;
    const int t = threadIdx.x;   // 0..255, t = h*64 + f
    __shared__ float bl[256], br[256];
    float v = g_feat[(size_t)n * HF + t];
    bl[t] = v * attn_l[t];
    br[t] = v * attn_r[t];
    __syncthreads();
    int f = t & 63;
#pragma unroll
    for (int st = 32; st >= 1; st >>= 1) {
        if (f < st) { bl[t] += bl[t + st]; br[t] += br[t + st]; }
        __syncthreads();
    }
    if (f == 0) {
        int h = t >> 6;
        g_el[n * HH + h] = bl[t];
        g_er[n * HH + h] = br[t];
    }
}

// ---------------- ee per etype ------------------------------------------------
__global__ void ee_kernel(const float* __restrict__ edge_emb,
                          const float* __restrict__ fc_e_w,
                          const float* __restrict__ attn_e)
{
    int t = threadIdx.x;
    if (t >= NT * HH) return;
    int tt = t >> 2, h = t & 3;
    float sum = 0.f;
    for (int e = 0; e < EFD; e++) {
        float ef = 0.f;
#pragma unroll 8
        for (int k = 0; k < EFD; k++)
            ef += edge_emb[tt * EFD + k] * fc_e_w[k * (HH * EFD) + h * EFD + e];
        sum += ef * attn_e[h * EFD + e];
    }
    g_ee[tt * HH + h] = sum;
}

// ---------------- CSR build ---------------------------------------------------
__global__ void zero_cnt_kernel()
{
    int i = blockIdx.x * blockDim.x + threadIdx.x;
    if (i <= NN) g_cnt[i] = 0;
}

__global__ void count_kernel(const int* __restrict__ dst)
{
    int e = blockIdx.x * blockDim.x + threadIdx.x;
    if (e < EE) atomicAdd(&g_cnt[dst[e]], 1);
}

#define SCAN_B 1024
#define NSCAN ((NN + SCAN_B - 1) / SCAN_B)   // 49

__global__ void scan1_kernel()
{
    __shared__ int s[SCAN_B];
    int b = blockIdx.x, tid = threadIdx.x;
    int idx = b * SCAN_B + tid;
    int v = (idx < NN) ? g_cnt[idx] : 0;
    s[tid] = v;
    __syncthreads();
    for (int off = 1; off < SCAN_B; off <<= 1) {
        int tmp = (tid >= off) ? s[tid - off] : 0;
        __syncthreads();
        s[tid] += tmp;
        __syncthreads();
    }
    if (idx < NN) g_off[idx] = s[tid] - v;   // exclusive within block
    if (tid == SCAN_B - 1) g_bsum[b] = s[tid];
}

__global__ void scan2_kernel()
{
    if (threadIdx.x == 0) {
        int acc = 0;
        for (int b = 0; b < NSCAN; b++) { g_bpre[b] = acc; acc += g_bsum[b]; }
        g_bpre[NSCAN] = acc;
    }
}

__global__ void scan3_kernel()
{
    int idx = blockIdx.x * blockDim.x + threadIdx.x;
    if (idx < NN) {
        int v = g_off[idx] + g_bpre[idx >> 10];
        g_off[idx] = v;
        g_cursor[idx] = v;
    } else if (idx == NN) {
        g_off[NN] = g_bpre[NSCAN];
    }
}

__global__ void scatter_kernel(const int* __restrict__ dst)
{
    int e = blockIdx.x * blockDim.x + threadIdx.x;
    if (e < EE) {
        int pos = atomicAdd(&g_cursor[dst[e]], 1);
        g_eids[pos] = e;
    }
}

// ---------------- fused edge-softmax + aggregation ---------------------------
__global__ void __launch_bounds__(256)
aggregate_kernel(const int* __restrict__ src, const int* __restrict__ etype,
                 float* __restrict__ out_rst, float* __restrict__ out_a)
{
    const int d   = blockIdx.x;
    const int tid = threadIdx.x;
    const int off = g_off[d];
    const int deg = g_off[d + 1] - off;

    if (deg == 0) { out_rst[(size_t)d * HF + tid] = 0.f; return; }

    __shared__ float er_sh[HH];
    __shared__ float ee_sh[NT * HH];
    __shared__ float m_sh[256], s_sh[256];
    __shared__ float Mh[HH], Sh[HH];
    __shared__ float w_sh[64 * HH];
    __shared__ int   src_sh[64];

    if (tid < HH)       er_sh[tid] = g_er[d * HH + tid];
    if (tid < NT * HH)  ee_sh[tid] = g_ee[tid];
    __syncthreads();

    const int h = tid & 3;          // head (pass-1 / weight mapping)
    const int g = tid >> 2;         // edge group 0..63

    // pass 1: online softmax (max, sum) per head over this dst's edges
    float m = -INFINITY, s = 0.f;
    for (int i = g; i < deg; i += 64) {
        int e  = g_eids[off + i];
        int sv = src[e];
        int tp = etype[e];
        float x = g_el[sv * HH + h] + er_sh[h] + ee_sh[tp * HH + h];
        x = x > 0.f ? x : SLOPE * x;
        if (x > m) { s = s * expf(m - x) + 1.f; m = x; }
        else       { s += expf(x - m); }
    }
    m_sh[tid] = m; s_sh[tid] = s;
    __syncthreads();
    for (int st = 128; st >= 4; st >>= 1) {
        if (tid < st) {
            float m1 = m_sh[tid], s1 = s_sh[tid];
            float m2 = m_sh[tid + st], s2 = s_sh[tid + st];
            float M = fmaxf(m1, m2);
            if (M > -INFINITY) {
                float S = 0.f;
                if (m1 > -INFINITY) S += s1 * expf(m1 - M);
                if (m2 > -INFINITY) S += s2 * expf(m2 - M);
                m_sh[tid] = M; s_sh[tid] = S;
            }
        }
        __syncthreads();
    }
    if (tid < HH) { Mh[tid] = m_sh[tid]; Sh[tid] = s_sh[tid]; }
    __syncthreads();

    // pass 2: chunked weight compute + weighted gather
    const int hh = tid >> 6;        // head (accumulation mapping)
    float acc = 0.f;

    for (int base = 0; base < deg; base += 64) {
        int cnt = min(64, deg - base);
        if (g < cnt) {
            int e  = g_eids[off + base + g];
            int sv = src[e];
            int tp = etype[e];
            if (h == 0) src_sh[g] = sv;
            float x = g_el[sv * HH + h] + er_sh[h] + ee_sh[tp * HH + h];
            x = x > 0.f ? x : SLOPE * x;
            float w = expf(x - Mh[h]) / Sh[h];
            w_sh[g * HH + h] = w;
            out_a[(size_t)e * HH + h] = w;
        }
        __syncthreads();
#pragma unroll 4
        for (int i = 0; i < cnt; i++) {
            acc += w_sh[i * HH + hh] * __ldg(&g_feat[(size_t)src_sh[i] * HF + tid]);
        }
        __syncthreads();
    }
    out_rst[(size_t)d * HF + tid] = acc;
}

// ---------------- launch ------------------------------------------------------
extern "C" void kernel_launch(void* const* d_in, const int* in_sizes, int n_in,
                              void* d_out, int out_size)
{
    const float* nfeat    = (const float*)d_in[0];
    const float* fc_w     = (const float*)d_in[1];
    const float* fc_e_w   = (const float*)d_in[2];
    const float* attn_l   = (const float*)d_in[3];
    const float* attn_r   = (const float*)d_in[4];
    const float* attn_e   = (const float*)d_in[5];
    const float* edge_emb = (const float*)d_in[6];
    const int*   src      = (const int*)d_in[7];
    const int*   dst      = (const int*)d_in[8];
    const int*   etype    = (const int*)d_in[9];

    float* out_rst = (float*)d_out;                       // [N, H, F]
    float* out_a   = (float*)d_out + (size_t)NN * HF;     // [E, H]

    float* feat_ptr;
    cudaGetSymbolAddress((void**)&feat_ptr, g_feat);

    // 1) node projection GEMM
    {
        dim3 grid((NN + BM - 1) / BM, HF / BN);
        sgemm_kernel<<<grid, 256>>>(nfeat, fc_w, feat_ptr, NN);
    }
    // 2) per-node attention halves
    elr_kernel<<<NN, 256>>>(attn_l, attn_r);
    // 3) per-etype attention term
    ee_kernel<<<1, 32>>>(edge_emb, fc_e_w, attn_e);
    // 4) CSR build: zero -> count -> scan -> scatter
    zero_cnt_kernel<<<(NN + 256) / 256, 256>>>();
    count_kernel<<<(EE + 255) / 256, 256>>>(dst);
    scan1_kernel<<<NSCAN, SCAN_B>>>();
    scan2_kernel<<<1, 32>>>();
    scan3_kernel<<<(NN + 256) / 256, 256>>>();
    scatter_kernel<<<(EE + 255) / 256, 256>>>(dst);
    // 5) fused softmax + aggregation, one block per dst node
    aggregate_kernel<<<NN, 256>>>(src, etype, out_rst, out_a);
}

// round 3
// speedup vs baseline: 1.3100x; 1.3100x over previous
#include <cuda_runtime.h>
#include <cuda_bf16.h>
#include <math.h>
#include <stdint.h>

// Problem constants
#define NN   50000
#define EE   800000
#define IND  256
#define HH   4
#define FF   64
#define HF   256
#define EFD  64
#define NT   8
#define SLOPE 0.2f

// ---------------- scratch ----------------------------------------------------
__device__ float g_feat[NN * HF];
__device__ float g_el[NN * HH];
__device__ float g_er[NN * HH];
__device__ float g_ee[NT * HH];
__device__ int   g_cnt[NN + 1];
__device__ int   g_off[NN + 1];
__device__ int   g_cursor[NN];
__device__ int   g_eids[EE];
__device__ int   g_bsum[64];
__device__ int   g_bpre[65];

// ---------------- helpers -----------------------------------------------------
__device__ __forceinline__ uint32_t smem_u32(const void* p) {
    uint32_t a;
    asm("{ .reg .u64 t; cvta.to.shared.u64 t, %1; cvt.u32.u64 %0, t; }"
        : "=r"(a) : "l"(p));
    return a;
}
__device__ __forceinline__ void ldmatrix_x4(uint32_t* r, uint32_t addr) {
    asm volatile("ldmatrix.sync.aligned.m8n8.x4.shared.b16 {%0,%1,%2,%3}, [%4];"
                 : "=r"(r[0]), "=r"(r[1]), "=r"(r[2]), "=r"(r[3]) : "r"(addr));
}
__device__ __forceinline__ void ldmatrix_x4_t(uint32_t* r, uint32_t addr) {
    asm volatile("ldmatrix.sync.aligned.m8n8.x4.trans.shared.b16 {%0,%1,%2,%3}, [%4];"
                 : "=r"(r[0]), "=r"(r[1]), "=r"(r[2]), "=r"(r[3]) : "r"(addr));
}
__device__ __forceinline__ void mma_bf16(float* c, const uint32_t* a,
                                         uint32_t b0, uint32_t b1) {
    asm volatile(
        "mma.sync.aligned.m16n8k16.row.col.f32.bf16.bf16.f32 "
        "{%0,%1,%2,%3}, {%4,%5,%6,%7}, {%8,%9}, {%0,%1,%2,%3};"
        : "+f"(c[0]), "+f"(c[1]), "+f"(c[2]), "+f"(c[3])
        : "r"(a[0]), "r"(a[1]), "r"(a[2]), "r"(a[3]), "r"(b0), "r"(b1));
}
__device__ __forceinline__ uint32_t pack_hi(float a, float b) {
    return ((uint32_t)__bfloat16_as_ushort(__float2bfloat16_rn(b)) << 16) |
           (uint32_t)__bfloat16_as_ushort(__float2bfloat16_rn(a));
}
__device__ __forceinline__ uint32_t pack_lo(float a, float b) {
    float ar = a - __bfloat162float(__float2bfloat16_rn(a));
    float br = b - __bfloat162float(__float2bfloat16_rn(b));
    return ((uint32_t)__bfloat16_as_ushort(__float2bfloat16_rn(br)) << 16) |
           (uint32_t)__bfloat16_as_ushort(__float2bfloat16_rn(ar));
}

// ---------------- bf16-split GEMM via mma.sync -------------------------------
// C[M,256] = A[M,256] @ B[256,256];  C fp32, split A=A1+A2, B=B1+B2 (bf16),
// accumulate A1B1 + A1B2 + A2B1 in fp32.
#define BM 128
#define BN 128
#define BK 32
#define AST 40    // A smem row stride, bf16 units (80 B)  -> conflict-free ldmatrix
#define BST 136   // B smem row stride, bf16 units (272 B) -> conflict-free ldmatrix

__global__ void __launch_bounds__(256)
gemm_mma_kernel(const float* __restrict__ A, const float* __restrict__ Bw,
                float* __restrict__ C, int M)
{
    __shared__ __align__(16) char sA1[BM * AST * 2];
    __shared__ __align__(16) char sA2[BM * AST * 2];
    __shared__ __align__(16) char sB1[BK * BST * 2];
    __shared__ __align__(16) char sB2[BK * BST * 2];

    const int tid  = threadIdx.x;
    const int wid  = tid >> 5;
    const int lane = tid & 31;
    const int m0 = blockIdx.x * BM;
    const int n0 = blockIdx.y * BN;

    const int wm = (wid & 1) * 64;   // warp m offset in tile
    const int wn = (wid >> 1) * 32;  // warp n offset in tile

    float acc[4][4][4];
#pragma unroll
    for (int i = 0; i < 4; i++)
#pragma unroll
        for (int j = 0; j < 4; j++)
#pragma unroll
            for (int r = 0; r < 4; r++) acc[i][j][r] = 0.f;

    // global-load mappings
    const int a_row  = tid >> 1;            // 0..127
    const int a_colb = (tid & 1) * 16;      // 0 / 16
    const int a_gr   = m0 + a_row;
    const int b_kr = tid >> 3;              // 0..31
    const int b_nb = (tid & 7) * 16;        // 0..112

    // ldmatrix lane addressing
    const int mat  = lane >> 3;
    const int l8   = lane & 7;
    const int a_mrow = (mat & 1) * 8 + l8;  // row within 16-row a-frag
    const int a_koff = (mat >> 1) * 8;      // 0 / 8 (k)
    const int b_krow = (mat & 1) * 8 + l8;  // k row within 16
    const int b_noff = (mat >> 1) * 8;      // 0 / 8 (n)

    const uint32_t sa1 = smem_u32(sA1), sa2 = smem_u32(sA2);
    const uint32_t sb1 = smem_u32(sB1), sb2 = smem_u32(sB2);

    for (int k0 = 0; k0 < IND; k0 += BK) {
        // ---- A tile 128x32 : fp32 -> hi/lo bf16
        {
            float4 v[4];
            if (a_gr < M) {
                const float4* p = (const float4*)(A + (size_t)a_gr * IND + k0 + a_colb);
#pragma unroll
                for (int q = 0; q < 4; q++) v[q] = p[q];
            } else {
#pragma unroll
                for (int q = 0; q < 4; q++) v[q] = make_float4(0, 0, 0, 0);
            }
            uint32_t hi[8], lo[8];
#pragma unroll
            for (int q = 0; q < 4; q++) {
                hi[2 * q]     = pack_hi(v[q].x, v[q].y);
                hi[2 * q + 1] = pack_hi(v[q].z, v[q].w);
                lo[2 * q]     = pack_lo(v[q].x, v[q].y);
                lo[2 * q + 1] = pack_lo(v[q].z, v[q].w);
            }
            char* d1 = sA1 + (a_row * AST + a_colb) * 2;
            char* d2 = sA2 + (a_row * AST + a_colb) * 2;
            ((uint4*)d1)[0] = make_uint4(hi[0], hi[1], hi[2], hi[3]);
            ((uint4*)d1)[1] = make_uint4(hi[4], hi[5], hi[6], hi[7]);
            ((uint4*)d2)[0] = make_uint4(lo[0], lo[1], lo[2], lo[3]);
            ((uint4*)d2)[1] = make_uint4(lo[4], lo[5], lo[6], lo[7]);
        }
        // ---- B tile 32x128 : fp32 -> hi/lo bf16
        {
            const float4* p = (const float4*)(Bw + (size_t)(k0 + b_kr) * HF + n0 + b_nb);
            float4 v[4];
#pragma unroll
            for (int q = 0; q < 4; q++) v[q] = p[q];
            uint32_t hi[8], lo[8];
#pragma unroll
            for (int q = 0; q < 4; q++) {
                hi[2 * q]     = pack_hi(v[q].x, v[q].y);
                hi[2 * q + 1] = pack_hi(v[q].z, v[q].w);
                lo[2 * q]     = pack_lo(v[q].x, v[q].y);
                lo[2 * q + 1] = pack_lo(v[q].z, v[q].w);
            }
            char* d1 = sB1 + (b_kr * BST + b_nb) * 2;
            char* d2 = sB2 + (b_kr * BST + b_nb) * 2;
            ((uint4*)d1)[0] = make_uint4(hi[0], hi[1], hi[2], hi[3]);
            ((uint4*)d1)[1] = make_uint4(hi[4], hi[5], hi[6], hi[7]);
            ((uint4*)d2)[0] = make_uint4(lo[0], lo[1], lo[2], lo[3]);
            ((uint4*)d2)[1] = make_uint4(lo[4], lo[5], lo[6], lo[7]);
        }
        __syncthreads();

        // ---- two k16 steps per chunk
#pragma unroll
        for (int kk = 0; kk < 2; kk++) {
            uint32_t a1[4][4], a2[4][4], b1[2][4], b2[2][4];
#pragma unroll
            for (int i = 0; i < 4; i++) {
                uint32_t off = ((wm + i * 16 + a_mrow) * AST + kk * 16 + a_koff) * 2;
                ldmatrix_x4(a1[i], sa1 + off);
                ldmatrix_x4(a2[i], sa2 + off);
            }
#pragma unroll
            for (int j2 = 0; j2 < 2; j2++) {
                uint32_t off = ((kk * 16 + b_krow) * BST + wn + j2 * 16 + b_noff) * 2;
                ldmatrix_x4_t(b1[j2], sb1 + off);
                ldmatrix_x4_t(b2[j2], sb2 + off);
            }
#pragma unroll
            for (int i = 0; i < 4; i++) {
#pragma unroll
                for (int j2 = 0; j2 < 2; j2++) {
                    // n-octet 2*j2 -> regs {0,1}; 2*j2+1 -> regs {2,3}
                    mma_bf16(acc[i][2 * j2],     a1[i], b1[j2][0], b1[j2][1]);
                    mma_bf16(acc[i][2 * j2],     a1[i], b2[j2][0], b2[j2][1]);
                    mma_bf16(acc[i][2 * j2],     a2[i], b1[j2][0], b1[j2][1]);
                    mma_bf16(acc[i][2 * j2 + 1], a1[i], b1[j2][2], b1[j2][3]);
                    mma_bf16(acc[i][2 * j2 + 1], a1[i], b2[j2][2], b2[j2][3]);
                    mma_bf16(acc[i][2 * j2 + 1], a2[i], b1[j2][2], b1[j2][3]);
                }
            }
        }
        __syncthreads();
    }

    // ---- epilogue: c-frag scatter to C
    const int crow = lane >> 2;
    const int ccol = (lane & 3) * 2;
#pragma unroll
    for (int i = 0; i < 4; i++) {
        int r0 = m0 + wm + i * 16 + crow;
#pragma unroll
        for (int j = 0; j < 4; j++) {
            int c = n0 + wn + j * 8 + ccol;
            if (r0 < M)
                *(float2*)(C + (size_t)r0 * HF + c) = make_float2(acc[i][j][0], acc[i][j][1]);
            if (r0 + 8 < M)
                *(float2*)(C + (size_t)(r0 + 8) * HF + c) = make_float2(acc[i][j][2], acc[i][j][3]);
        }
    }
}

// ---------------- el / er: warp per node -------------------------------------
__global__ void elr_kernel(const float* __restrict__ attn_l,
                           const float* __restrict__ attn_r)
{
    int w = (blockIdx.x * blockDim.x + threadIdx.x) >> 5;
    int lane = threadIdx.x & 31;
    if (w >= NN) return;
    const float4* fp = (const float4*)(g_feat + (size_t)w * HF + lane * 8);
    float4 v0 = fp[0], v1 = fp[1];
    const float4* alp = (const float4*)(attn_l + lane * 8);
    const float4* arp = (const float4*)(attn_r + lane * 8);
    float4 a0 = alp[0], a1 = alp[1], b0 = arp[0], b1 = arp[1];
    float sl = v0.x * a0.x + v0.y * a0.y + v0.z * a0.z + v0.w * a0.w
             + v1.x * a1.x + v1.y * a1.y + v1.z * a1.z + v1.w * a1.w;
    float sr = v0.x * b0.x + v0.y * b0.y + v0.z * b0.z + v0.w * b0.w
             + v1.x * b1.x + v1.y * b1.y + v1.z * b1.z + v1.w * b1.w;
#pragma unroll
    for (int o = 4; o >= 1; o >>= 1) {
        sl += __shfl_xor_sync(0xffffffffu, sl, o);
        sr += __shfl_xor_sync(0xffffffffu, sr, o);
    }
    if ((lane & 7) == 0) {
        int h = lane >> 3;
        g_el[w * HH + h] = sl;
        g_er[w * HH + h] = sr;
    }
}

// ---------------- ee per etype ------------------------------------------------
__global__ void ee_kernel(const float* __restrict__ edge_emb,
                          const float* __restrict__ fc_e_w,
                          const float* __restrict__ attn_e)
{
    int t = threadIdx.x;
    if (t >= NT * HH) return;
    int tt = t >> 2, h = t & 3;
    float sum = 0.f;
    for (int e = 0; e < EFD; e++) {
        float ef = 0.f;
#pragma unroll 8
        for (int k = 0; k < EFD; k++)
            ef += edge_emb[tt * EFD + k] * fc_e_w[k * (HH * EFD) + h * EFD + e];
        sum += ef * attn_e[h * EFD + e];
    }
    g_ee[tt * HH + h] = sum;
}

// ---------------- CSR build ---------------------------------------------------
__global__ void zero_cnt_kernel()
{
    int i = blockIdx.x * blockDim.x + threadIdx.x;
    if (i <= NN) g_cnt[i] = 0;
}

__global__ void count_kernel(const int* __restrict__ dst)
{
    int e = blockIdx.x * blockDim.x + threadIdx.x;
    if (e < EE) atomicAdd(&g_cnt[dst[e]], 1);
}

#define SCAN_B 1024
#define NSCAN ((NN + SCAN_B - 1) / SCAN_B)

__global__ void scan1_kernel()
{
    __shared__ int s[SCAN_B];
    int b = blockIdx.x, tid = threadIdx.x;
    int idx = b * SCAN_B + tid;
    int v = (idx < NN) ? g_cnt[idx] : 0;
    s[tid] = v;
    __syncthreads();
    for (int off = 1; off < SCAN_B; off <<= 1) {
        int tmp = (tid >= off) ? s[tid - off] : 0;
        __syncthreads();
        s[tid] += tmp;
        __syncthreads();
    }
    if (idx < NN) g_off[idx] = s[tid] - v;
    if (tid == SCAN_B - 1) g_bsum[b] = s[tid];
}

__global__ void scan2_kernel()
{
    if (threadIdx.x == 0) {
        int acc = 0;
        for (int b = 0; b < NSCAN; b++) { g_bpre[b] = acc; acc += g_bsum[b]; }
        g_bpre[NSCAN] = acc;
    }
}

__global__ void scan3_kernel()
{
    int idx = blockIdx.x * blockDim.x + threadIdx.x;
    if (idx < NN) {
        int v = g_off[idx] + g_bpre[idx >> 10];
        g_off[idx] = v;
        g_cursor[idx] = v;
    } else if (idx == NN) {
        g_off[NN] = g_bpre[NSCAN];
    }
}

__global__ void scatter_kernel(const int* __restrict__ dst)
{
    int e = blockIdx.x * blockDim.x + threadIdx.x;
    if (e < EE) {
        int pos = atomicAdd(&g_cursor[dst[e]], 1);
        g_eids[pos] = e;
    }
}

// ---------------- fused edge-softmax + aggregation ---------------------------
__global__ void __launch_bounds__(256)
aggregate_kernel(const int* __restrict__ src, const int* __restrict__ etype,
                 float* __restrict__ out_rst, float* __restrict__ out_a)
{
    const int d   = blockIdx.x;
    const int tid = threadIdx.x;
    const int off = g_off[d];
    const int deg = g_off[d + 1] - off;

    if (deg == 0) { out_rst[(size_t)d * HF + tid] = 0.f; return; }

    __shared__ float er_sh[HH];
    __shared__ float ee_sh[NT * HH];
    __shared__ float m_sh[256], s_sh[256];
    __shared__ float Mh[HH], Sh[HH];
    __shared__ float w_sh[64 * HH];
    __shared__ int   src_sh[64];

    if (tid < HH)      er_sh[tid] = g_er[d * HH + tid];
    if (tid < NT * HH) ee_sh[tid] = g_ee[tid];
    __syncthreads();

    const int h = tid & 3;
    const int g = tid >> 2;

    float m = -INFINITY, s = 0.f;
    for (int i = g; i < deg; i += 64) {
        int e  = g_eids[off + i];
        int sv = src[e];
        int tp = etype[e];
        float x = g_el[sv * HH + h] + er_sh[h] + ee_sh[tp * HH + h];
        x = x > 0.f ? x : SLOPE * x;
        if (x > m) { s = s * expf(m - x) + 1.f; m = x; }
        else       { s += expf(x - m); }
    }
    m_sh[tid] = m; s_sh[tid] = s;
    __syncthreads();
    for (int st = 128; st >= 4; st >>= 1) {
        if (tid < st) {
            float m1 = m_sh[tid], s1 = s_sh[tid];
            float m2 = m_sh[tid + st], s2 = s_sh[tid + st];
            float M = fmaxf(m1, m2);
            if (M > -INFINITY) {
                float S = 0.f;
                if (m1 > -INFINITY) S += s1 * expf(m1 - M);
                if (m2 > -INFINITY) S += s2 * expf(m2 - M);
                m_sh[tid] = M; s_sh[tid] = S;
            }
        }
        __syncthreads();
    }
    if (tid < HH) { Mh[tid] = m_sh[tid]; Sh[tid] = s_sh[tid]; }
    __syncthreads();

    const int hh = tid >> 6;
    float acc = 0.f;

    for (int base = 0; base < deg; base += 64) {
        int cnt = min(64, deg - base);
        if (g < cnt) {
            int e  = g_eids[off + base + g];
            int sv = src[e];
            int tp = etype[e];
            if (h == 0) src_sh[g] = sv;
            float x = g_el[sv * HH + h] + er_sh[h] + ee_sh[tp * HH + h];
            x = x > 0.f ? x : SLOPE * x;
            float w = expf(x - Mh[h]) / Sh[h];
            w_sh[g * HH + h] = w;
            out_a[(size_t)e * HH + h] = w;
        }
        __syncthreads();
#pragma unroll 4
        for (int i = 0; i < cnt; i++) {
            acc += w_sh[i * HH + hh] * __ldg(&g_feat[(size_t)src_sh[i] * HF + tid]);
        }
        __syncthreads();
    }
    out_rst[(size_t)d * HF + tid] = acc;
}

// ---------------- launch ------------------------------------------------------
extern "C" void kernel_launch(void* const* d_in, const int* in_sizes, int n_in,
                              void* d_out, int out_size)
{
    const float* nfeat    = (const float*)d_in[0];
    const float* fc_w     = (const float*)d_in[1];
    const float* fc_e_w   = (const float*)d_in[2];
    const float* attn_l   = (const float*)d_in[3];
    const float* attn_r   = (const float*)d_in[4];
    const float* attn_e   = (const float*)d_in[5];
    const float* edge_emb = (const float*)d_in[6];
    const int*   src      = (const int*)d_in[7];
    const int*   dst      = (const int*)d_in[8];
    const int*   etype    = (const int*)d_in[9];

    float* out_rst = (float*)d_out;
    float* out_a   = (float*)d_out + (size_t)NN * HF;

    float* feat_ptr;
    cudaGetSymbolAddress((void**)&feat_ptr, g_feat);

    // 1) node projection GEMM (tensor cores via mma.sync, bf16 split)
    {
        dim3 grid((NN + BM - 1) / BM, HF / BN);
        gemm_mma_kernel<<<grid, 256>>>(nfeat, fc_w, feat_ptr, NN);
    }
    // 2) per-node attention halves
    elr_kernel<<<(NN * 32 + 255) / 256, 256>>>(attn_l, attn_r);
    // 3) per-etype attention term
    ee_kernel<<<1, 32>>>(edge_emb, fc_e_w, attn_e);
    // 4) CSR build
    zero_cnt_kernel<<<(NN + 256) / 256, 256>>>();
    count_kernel<<<(EE + 255) / 256, 256>>>(dst);
    scan1_kernel<<<NSCAN, SCAN_B>>>();
    scan2_kernel<<<1, 32>>>();
    scan3_kernel<<<(NN + 256) / 256, 256>>>();
    scatter_kernel<<<(EE + 255) / 256, 256>>>(dst);
    // 5) fused softmax + aggregation
    aggregate_kernel<<<NN, 256>>>(src, etype, out_rst, out_a);
}

// round 4
// speedup vs baseline: 1.3313x; 1.0163x over previous
#include <cuda_runtime.h>
#include <cuda_bf16.h>
#include <math.h>
#include <stdint.h>

// Problem constants
#define NN   50000
#define EE   800000
#define IND  256
#define HH   4
#define FF   64
#define HF   256
#define EFD  64
#define NT   8
#define SLOPE 0.2f

// ---------------- scratch ----------------------------------------------------
__device__ float g_feat[NN * HF];
__device__ float g_el[NN * HH];
__device__ float g_er[NN * HH];
__device__ float g_ee[NT * HH];
__device__ float g_score[(size_t)EE * HH];   // leaky-relu'd scores in CSR order
__device__ int   g_cnt[NN + 1];
__device__ int   g_off[NN + 1];
__device__ int   g_cursor[NN];
__device__ int   g_eids[EE];
__device__ int   g_bsum[64];
__device__ int   g_bpre[65];

// ---------------- helpers -----------------------------------------------------
__device__ __forceinline__ uint32_t smem_u32(const void* p) {
    uint32_t a;
    asm("{ .reg .u64 t; cvta.to.shared.u64 t, %1; cvt.u32.u64 %0, t; }"
        : "=r"(a) : "l"(p));
    return a;
}
__device__ __forceinline__ void ldmatrix_x4(uint32_t* r, uint32_t addr) {
    asm volatile("ldmatrix.sync.aligned.m8n8.x4.shared.b16 {%0,%1,%2,%3}, [%4];"
                 : "=r"(r[0]), "=r"(r[1]), "=r"(r[2]), "=r"(r[3]) : "r"(addr));
}
__device__ __forceinline__ void ldmatrix_x4_t(uint32_t* r, uint32_t addr) {
    asm volatile("ldmatrix.sync.aligned.m8n8.x4.trans.shared.b16 {%0,%1,%2,%3}, [%4];"
                 : "=r"(r[0]), "=r"(r[1]), "=r"(r[2]), "=r"(r[3]) : "r"(addr));
}
__device__ __forceinline__ void mma_bf16(float* c, const uint32_t* a,
                                         uint32_t b0, uint32_t b1) {
    asm volatile(
        "mma.sync.aligned.m16n8k16.row.col.f32.bf16.bf16.f32 "
        "{%0,%1,%2,%3}, {%4,%5,%6,%7}, {%8,%9}, {%0,%1,%2,%3};"
        : "+f"(c[0]), "+f"(c[1]), "+f"(c[2]), "+f"(c[3])
        : "r"(a[0]), "r"(a[1]), "r"(a[2]), "r"(a[3]), "r"(b0), "r"(b1));
}
__device__ __forceinline__ uint32_t pack_hi(float a, float b) {
    return ((uint32_t)__bfloat16_as_ushort(__float2bfloat16_rn(b)) << 16) |
           (uint32_t)__bfloat16_as_ushort(__float2bfloat16_rn(a));
}
__device__ __forceinline__ uint32_t pack_lo(float a, float b) {
    float ar = a - __bfloat162float(__float2bfloat16_rn(a));
    float br = b - __bfloat162float(__float2bfloat16_rn(b));
    return ((uint32_t)__bfloat16_as_ushort(__float2bfloat16_rn(br)) << 16) |
           (uint32_t)__bfloat16_as_ushort(__float2bfloat16_rn(ar));
}

// ---------------- bf16-split GEMM via mma.sync (register-prefetch pipelined) --
#define BM 128
#define BN 128
#define BK 32
#define AST 40    // A smem row stride (bf16 units) -> conflict-free ldmatrix
#define BST 136   // B smem row stride (bf16 units) -> conflict-free ldmatrix

__global__ void __launch_bounds__(256)
gemm_mma_kernel(const float* __restrict__ A, const float* __restrict__ Bw,
                float* __restrict__ C, int M)
{
    __shared__ __align__(16) char sA1[BM * AST * 2];
    __shared__ __align__(16) char sA2[BM * AST * 2];
    __shared__ __align__(16) char sB1[BK * BST * 2];
    __shared__ __align__(16) char sB2[BK * BST * 2];

    const int tid  = threadIdx.x;
    const int wid  = tid >> 5;
    const int lane = tid & 31;
    const int m0 = blockIdx.x * BM;
    const int n0 = blockIdx.y * BN;

    const int wm = (wid & 1) * 64;
    const int wn = (wid >> 1) * 32;

    float acc[4][4][4];
#pragma unroll
    for (int i = 0; i < 4; i++)
#pragma unroll
        for (int j = 0; j < 4; j++)
#pragma unroll
            for (int r = 0; r < 4; r++) acc[i][j][r] = 0.f;

    const int a_row  = tid >> 1;
    const int a_colb = (tid & 1) * 16;
    const int a_gr   = m0 + a_row;
    const int b_kr = tid >> 3;
    const int b_nb = (tid & 7) * 16;

    const int mat  = lane >> 3;
    const int l8   = lane & 7;
    const int a_mrow = (mat & 1) * 8 + l8;
    const int a_koff = (mat >> 1) * 8;
    const int b_krow = (mat & 1) * 8 + l8;
    const int b_noff = (mat >> 1) * 8;

    const uint32_t sa1 = smem_u32(sA1), sa2 = smem_u32(sA2);
    const uint32_t sb1 = smem_u32(sB1), sb2 = smem_u32(sB2);

    float4 va[4], vb[4];
    // prologue: load chunk 0
    {
        if (a_gr < M) {
            const float4* p = (const float4*)(A + (size_t)a_gr * IND + a_colb);
#pragma unroll
            for (int q = 0; q < 4; q++) va[q] = p[q];
        } else {
#pragma unroll
            for (int q = 0; q < 4; q++) va[q] = make_float4(0, 0, 0, 0);
        }
        const float4* p = (const float4*)(Bw + (size_t)b_kr * HF + n0 + b_nb);
#pragma unroll
        for (int q = 0; q < 4; q++) vb[q] = p[q];
    }

    for (int c = 0; c < IND / BK; c++) {
        // ---- convert current chunk regs -> smem (hi/lo bf16)
        {
            uint32_t hi[8], lo[8];
#pragma unroll
            for (int q = 0; q < 4; q++) {
                hi[2 * q]     = pack_hi(va[q].x, va[q].y);
                hi[2 * q + 1] = pack_hi(va[q].z, va[q].w);
                lo[2 * q]     = pack_lo(va[q].x, va[q].y);
                lo[2 * q + 1] = pack_lo(va[q].z, va[q].w);
            }
            char* d1 = sA1 + (a_row * AST + a_colb) * 2;
            char* d2 = sA2 + (a_row * AST + a_colb) * 2;
            ((uint4*)d1)[0] = make_uint4(hi[0], hi[1], hi[2], hi[3]);
            ((uint4*)d1)[1] = make_uint4(hi[4], hi[5], hi[6], hi[7]);
            ((uint4*)d2)[0] = make_uint4(lo[0], lo[1], lo[2], lo[3]);
            ((uint4*)d2)[1] = make_uint4(lo[4], lo[5], lo[6], lo[7]);
#pragma unroll
            for (int q = 0; q < 4; q++) {
                hi[2 * q]     = pack_hi(vb[q].x, vb[q].y);
                hi[2 * q + 1] = pack_hi(vb[q].z, vb[q].w);
                lo[2 * q]     = pack_lo(vb[q].x, vb[q].y);
                lo[2 * q + 1] = pack_lo(vb[q].z, vb[q].w);
            }
            char* e1 = sB1 + (b_kr * BST + b_nb) * 2;
            char* e2 = sB2 + (b_kr * BST + b_nb) * 2;
            ((uint4*)e1)[0] = make_uint4(hi[0], hi[1], hi[2], hi[3]);
            ((uint4*)e1)[1] = make_uint4(hi[4], hi[5], hi[6], hi[7]);
            ((uint4*)e2)[0] = make_uint4(lo[0], lo[1], lo[2], lo[3]);
            ((uint4*)e2)[1] = make_uint4(lo[4], lo[5], lo[6], lo[7]);
        }
        __syncthreads();

        // ---- prefetch next chunk into regs (LDGs overlap the MMA below)
        if (c + 1 < IND / BK) {
            const int k0 = (c + 1) * BK;
            if (a_gr < M) {
                const float4* p = (const float4*)(A + (size_t)a_gr * IND + k0 + a_colb);
#pragma unroll
                for (int q = 0; q < 4; q++) va[q] = p[q];
            } else {
#pragma unroll
                for (int q = 0; q < 4; q++) va[q] = make_float4(0, 0, 0, 0);
            }
            const float4* p = (const float4*)(Bw + (size_t)(k0 + b_kr) * HF + n0 + b_nb);
#pragma unroll
            for (int q = 0; q < 4; q++) vb[q] = p[q];
        }

        // ---- MMA over current smem
#pragma unroll
        for (int kk = 0; kk < 2; kk++) {
            uint32_t a1[4][4], a2[4][4], b1[2][4], b2[2][4];
#pragma unroll
            for (int i = 0; i < 4; i++) {
                uint32_t off = ((wm + i * 16 + a_mrow) * AST + kk * 16 + a_koff) * 2;
                ldmatrix_x4(a1[i], sa1 + off);
                ldmatrix_x4(a2[i], sa2 + off);
            }
#pragma unroll
            for (int j2 = 0; j2 < 2; j2++) {
                uint32_t off = ((kk * 16 + b_krow) * BST + wn + j2 * 16 + b_noff) * 2;
                ldmatrix_x4_t(b1[j2], sb1 + off);
                ldmatrix_x4_t(b2[j2], sb2 + off);
            }
#pragma unroll
            for (int i = 0; i < 4; i++) {
#pragma unroll
                for (int j2 = 0; j2 < 2; j2++) {
                    mma_bf16(acc[i][2 * j2],     a1[i], b1[j2][0], b1[j2][1]);
                    mma_bf16(acc[i][2 * j2],     a1[i], b2[j2][0], b2[j2][1]);
                    mma_bf16(acc[i][2 * j2],     a2[i], b1[j2][0], b1[j2][1]);
                    mma_bf16(acc[i][2 * j2 + 1], a1[i], b1[j2][2], b1[j2][3]);
                    mma_bf16(acc[i][2 * j2 + 1], a1[i], b2[j2][2], b2[j2][3]);
                    mma_bf16(acc[i][2 * j2 + 1], a2[i], b1[j2][2], b1[j2][3]);
                }
            }
        }
        __syncthreads();
    }

    const int crow = lane >> 2;
    const int ccol = (lane & 3) * 2;
#pragma unroll
    for (int i = 0; i < 4; i++) {
        int r0 = m0 + wm + i * 16 + crow;
#pragma unroll
        for (int j = 0; j < 4; j++) {
            int c = n0 + wn + j * 8 + ccol;
            if (r0 < M)
                *(float2*)(C + (size_t)r0 * HF + c) = make_float2(acc[i][j][0], acc[i][j][1]);
            if (r0 + 8 < M)
                *(float2*)(C + (size_t)(r0 + 8) * HF + c) = make_float2(acc[i][j][2], acc[i][j][3]);
        }
    }
}

// ---------------- el / er: warp per node -------------------------------------
__global__ void elr_kernel(const float* __restrict__ attn_l,
                           const float* __restrict__ attn_r)
{
    int w = (blockIdx.x * blockDim.x + threadIdx.x) >> 5;
    int lane = threadIdx.x & 31;
    if (w >= NN) return;
    const float4* fp = (const float4*)(g_feat + (size_t)w * HF + lane * 8);
    float4 v0 = fp[0], v1 = fp[1];
    const float4* alp = (const float4*)(attn_l + lane * 8);
    const float4* arp = (const float4*)(attn_r + lane * 8);
    float4 a0 = alp[0], a1 = alp[1], b0 = arp[0], b1 = arp[1];
    float sl = v0.x * a0.x + v0.y * a0.y + v0.z * a0.z + v0.w * a0.w
             + v1.x * a1.x + v1.y * a1.y + v1.z * a1.z + v1.w * a1.w;
    float sr = v0.x * b0.x + v0.y * b0.y + v0.z * b0.z + v0.w * b0.w
             + v1.x * b1.x + v1.y * b1.y + v1.z * b1.z + v1.w * b1.w;
#pragma unroll
    for (int o = 4; o >= 1; o >>= 1) {
        sl += __shfl_xor_sync(0xffffffffu, sl, o);
        sr += __shfl_xor_sync(0xffffffffu, sr, o);
    }
    if ((lane & 7) == 0) {
        int h = lane >> 3;
        g_el[w * HH + h] = sl;
        g_er[w * HH + h] = sr;
    }
}

// ---------------- ee per etype ------------------------------------------------
__global__ void ee_kernel(const float* __restrict__ edge_emb,
                          const float* __restrict__ fc_e_w,
                          const float* __restrict__ attn_e)
{
    int t = threadIdx.x;
    if (t >= NT * HH) return;
    int tt = t >> 2, h = t & 3;
    float sum = 0.f;
    for (int e = 0; e < EFD; e++) {
        float ef = 0.f;
#pragma unroll 8
        for (int k = 0; k < EFD; k++)
            ef += edge_emb[tt * EFD + k] * fc_e_w[k * (HH * EFD) + h * EFD + e];
        sum += ef * attn_e[h * EFD + e];
    }
    g_ee[tt * HH + h] = sum;
}

// ---------------- CSR build ---------------------------------------------------
__global__ void zero_cnt_kernel()
{
    int i = blockIdx.x * blockDim.x + threadIdx.x;
    if (i <= NN) g_cnt[i] = 0;
}

__global__ void count_kernel(const int* __restrict__ dst)
{
    int e = blockIdx.x * blockDim.x + threadIdx.x;
    if (e < EE) atomicAdd(&g_cnt[dst[e]], 1);
}

#define SCAN_B 1024
#define NSCAN ((NN + SCAN_B - 1) / SCAN_B)

__global__ void scan1_kernel()
{
    __shared__ int s[SCAN_B];
    int b = blockIdx.x, tid = threadIdx.x;
    int idx = b * SCAN_B + tid;
    int v = (idx < NN) ? g_cnt[idx] : 0;
    s[tid] = v;
    __syncthreads();
    for (int off = 1; off < SCAN_B; off <<= 1) {
        int tmp = (tid >= off) ? s[tid - off] : 0;
        __syncthreads();
        s[tid] += tmp;
        __syncthreads();
    }
    if (idx < NN) g_off[idx] = s[tid] - v;
    if (tid == SCAN_B - 1) g_bsum[b] = s[tid];
}

__global__ void scan2_kernel()
{
    if (threadIdx.x == 0) {
        int acc = 0;
        for (int b = 0; b < NSCAN; b++) { g_bpre[b] = acc; acc += g_bsum[b]; }
        g_bpre[NSCAN] = acc;
    }
}

__global__ void scan3_kernel()
{
    int idx = blockIdx.x * blockDim.x + threadIdx.x;
    if (idx < NN) {
        int v = g_off[idx] + g_bpre[idx >> 10];
        g_off[idx] = v;
        g_cursor[idx] = v;
    } else if (idx == NN) {
        g_off[NN] = g_bpre[NSCAN];
    }
}

// ---- scatter + per-edge score computation (CSR-ordered scores) --------------
__global__ void scatter_score_kernel(const int* __restrict__ src,
                                     const int* __restrict__ dst,
                                     const int* __restrict__ etype)
{
    int e = blockIdx.x * blockDim.x + threadIdx.x;
    if (e >= EE) return;
    int dv = dst[e];
    int pos = atomicAdd(&g_cursor[dv], 1);
    g_eids[pos] = e;
    int sv = src[e], tp = etype[e];
    float4 l = *(const float4*)&g_el[sv * HH];
    float4 r = *(const float4*)&g_er[dv * HH];
    float4 t = *(const float4*)&g_ee[tp * HH];
    float4 x;
    x.x = l.x + r.x + t.x;  x.x = x.x > 0.f ? x.x : SLOPE * x.x;
    x.y = l.y + r.y + t.y;  x.y = x.y > 0.f ? x.y : SLOPE * x.y;
    x.z = l.z + r.z + t.z;  x.z = x.z > 0.f ? x.z : SLOPE * x.z;
    x.w = l.w + r.w + t.w;  x.w = x.w > 0.f ? x.w : SLOPE * x.w;
    *(float4*)&g_score[(size_t)pos * HH] = x;
}

// ---------------- fused edge-softmax + aggregation ---------------------------
__global__ void __launch_bounds__(256)
aggregate_kernel(const int* __restrict__ src,
                 float* __restrict__ out_rst, float* __restrict__ out_a)
{
    const int d   = blockIdx.x;
    const int tid = threadIdx.x;
    const int off = g_off[d];
    const int deg = g_off[d + 1] - off;

    if (deg == 0) { out_rst[(size_t)d * HF + tid] = 0.f; return; }

    __shared__ float m_sh[256], s_sh[256];
    __shared__ float Mh[HH], Sh[HH];
    __shared__ float w_sh[64 * HH];
    __shared__ int   src_sh[64];

    const int h = tid & 3;
    const int g = tid >> 2;

    // pass 1: online softmax stats; contiguous score reads
    float m = -INFINITY, s = 0.f;
    for (int i = g; i < deg; i += 64) {
        float x = g_score[(size_t)(off + i) * HH + h];
        if (x > m) { s = s * __expf(m - x) + 1.f; m = x; }
        else       { s += __expf(x - m); }
    }
    m_sh[tid] = m; s_sh[tid] = s;
    __syncthreads();
    for (int st = 128; st >= 4; st >>= 1) {
        if (tid < st) {
            float m1 = m_sh[tid], s1 = s_sh[tid];
            float m2 = m_sh[tid + st], s2 = s_sh[tid + st];
            float M = fmaxf(m1, m2);
            if (M > -INFINITY) {
                float S = 0.f;
                if (m1 > -INFINITY) S += s1 * __expf(m1 - M);
                if (m2 > -INFINITY) S += s2 * __expf(m2 - M);
                m_sh[tid] = M; s_sh[tid] = S;
            }
        }
        __syncthreads();
    }
    if (tid < HH) { Mh[tid] = m_sh[tid]; Sh[tid] = 1.f / s_sh[tid]; }
    __syncthreads();

    const int hh = tid >> 6;
    float acc = 0.f;

    for (int base = 0; base < deg; base += 64) {
        int cnt = min(64, deg - base);
        if (g < cnt) {
            int p = off + base + g;
            int e = g_eids[p];
            float x = g_score[(size_t)p * HH + h];
            float w = __expf(x - Mh[h]) * Sh[h];
            w_sh[g * HH + h] = w;
            out_a[(size_t)e * HH + h] = w;
            if (h == 0) src_sh[g] = src[e];
        }
        __syncthreads();
#pragma unroll 4
        for (int i = 0; i < cnt; i++) {
            acc += w_sh[i * HH + hh] * __ldg(&g_feat[(size_t)src_sh[i] * HF + tid]);
        }
        __syncthreads();
    }
    out_rst[(size_t)d * HF + tid] = acc;
}

// ---------------- launch ------------------------------------------------------
extern "C" void kernel_launch(void* const* d_in, const int* in_sizes, int n_in,
                              void* d_out, int out_size)
{
    const float* nfeat    = (const float*)d_in[0];
    const float* fc_w     = (const float*)d_in[1];
    const float* fc_e_w   = (const float*)d_in[2];
    const float* attn_l   = (const float*)d_in[3];
    const float* attn_r   = (const float*)d_in[4];
    const float* attn_e   = (const float*)d_in[5];
    const float* edge_emb = (const float*)d_in[6];
    const int*   src      = (const int*)d_in[7];
    const int*   dst      = (const int*)d_in[8];
    const int*   etype    = (const int*)d_in[9];

    float* out_rst = (float*)d_out;
    float* out_a   = (float*)d_out + (size_t)NN * HF;

    float* feat_ptr;
    cudaGetSymbolAddress((void**)&feat_ptr, g_feat);

    // Launch order puts the GEMM at index 3 (the slot ncu captures).
    zero_cnt_kernel<<<(NN + 256) / 256, 256>>>();                 // 0
    count_kernel<<<(EE + 255) / 256, 256>>>(dst);                 // 1
    scan1_kernel<<<NSCAN, SCAN_B>>>();                            // 2
    {
        dim3 grid((NN + BM - 1) / BM, HF / BN);
        gemm_mma_kernel<<<grid, 256>>>(nfeat, fc_w, feat_ptr, NN);// 3  <- profiled
    }
    ee_kernel<<<1, 32>>>(edge_emb, fc_e_w, attn_e);               // 4
    scan2_kernel<<<1, 32>>>();                                    // 5
    scan3_kernel<<<(NN + 256) / 256, 256>>>();                    // 6
    elr_kernel<<<(NN * 32 + 255) / 256, 256>>>(attn_l, attn_r);   // 7
    scatter_score_kernel<<<(EE + 255) / 256, 256>>>(src, dst, etype); // 8
    aggregate_kernel<<<NN, 256>>>(src, out_rst, out_a);           // 9
}

// round 5
// speedup vs baseline: 1.4617x; 1.0980x over previous
#include <cuda_runtime.h>
#include <cuda_bf16.h>
#include <math.h>
#include <stdint.h>

// Problem constants
#define NN   50000
#define EE   800000
#define IND  256
#define HH   4
#define FF   64
#define HF   256
#define EFD  64
#define NT   8
#define SLOPE 0.2f

// ---------------- scratch ----------------------------------------------------
__device__ float g_feat[NN * HF];
__device__ float g_el[NN * HH];
__device__ float g_er[NN * HH];
__device__ float g_ee[NT * HH];
__device__ float g_sum[NN * HH];              // sum of exp(score) per (dst, head)
__device__ float g_score[(size_t)EE * HH];    // exp(score), CSR order
__device__ int   g_srcs[EE];                  // src node per CSR slot
__device__ int   g_eids[EE];                  // original edge id per CSR slot
__device__ __nv_bfloat16 g_B1[IND * HF];      // fc_w hi (bf16)
__device__ __nv_bfloat16 g_B2[IND * HF];      // fc_w lo (bf16)
__device__ int   g_cnt[NN + 1];
__device__ int   g_off[NN + 1];
__device__ int   g_cursor[NN];
__device__ int   g_bsum[64];
__device__ int   g_bpre[65];

// ---------------- helpers -----------------------------------------------------
__device__ __forceinline__ uint32_t smem_u32(const void* p) {
    uint32_t a;
    asm("{ .reg .u64 t; cvta.to.shared.u64 t, %1; cvt.u32.u64 %0, t; }"
        : "=r"(a) : "l"(p));
    return a;
}
__device__ __forceinline__ void ldmatrix_x4(uint32_t* r, uint32_t addr) {
    asm volatile("ldmatrix.sync.aligned.m8n8.x4.shared.b16 {%0,%1,%2,%3}, [%4];"
                 : "=r"(r[0]), "=r"(r[1]), "=r"(r[2]), "=r"(r[3]) : "r"(addr));
}
__device__ __forceinline__ void ldmatrix_x4_t(uint32_t* r, uint32_t addr) {
    asm volatile("ldmatrix.sync.aligned.m8n8.x4.trans.shared.b16 {%0,%1,%2,%3}, [%4];"
                 : "=r"(r[0]), "=r"(r[1]), "=r"(r[2]), "=r"(r[3]) : "r"(addr));
}
__device__ __forceinline__ void mma_bf16(float* c, const uint32_t* a,
                                         uint32_t b0, uint32_t b1) {
    asm volatile(
        "mma.sync.aligned.m16n8k16.row.col.f32.bf16.bf16.f32 "
        "{%0,%1,%2,%3}, {%4,%5,%6,%7}, {%8,%9}, {%0,%1,%2,%3};"
        : "+f"(c[0]), "+f"(c[1]), "+f"(c[2]), "+f"(c[3])
        : "r"(a[0]), "r"(a[1]), "r"(a[2]), "r"(a[3]), "r"(b0), "r"(b1));
}
__device__ __forceinline__ uint32_t pack_hi(float a, float b) {
    return ((uint32_t)__bfloat16_as_ushort(__float2bfloat16_rn(b)) << 16) |
           (uint32_t)__bfloat16_as_ushort(__float2bfloat16_rn(a));
}
__device__ __forceinline__ uint32_t pack_lo(float a, float b) {
    float ar = a - __bfloat162float(__float2bfloat16_rn(a));
    float br = b - __bfloat162float(__float2bfloat16_rn(b));
    return ((uint32_t)__bfloat16_as_ushort(__float2bfloat16_rn(br)) << 16) |
           (uint32_t)__bfloat16_as_ushort(__float2bfloat16_rn(ar));
}

// ---------------- B pre-conversion to bf16 hi/lo ------------------------------
__global__ void convert_b_kernel(const float* __restrict__ Bw)
{
    int i = (blockIdx.x * blockDim.x + threadIdx.x) * 4;
    float4 v = *(const float4*)(Bw + i);
    float f[4] = { v.x, v.y, v.z, v.w };
#pragma unroll
    for (int q = 0; q < 4; q++) {
        __nv_bfloat16 h = __float2bfloat16_rn(f[q]);
        g_B1[i + q] = h;
        g_B2[i + q] = __float2bfloat16_rn(f[q] - __bfloat162float(h));
    }
}

// ---------------- bf16-split GEMM via mma.sync --------------------------------
#define BM 128
#define BN 128
#define BK 32
#define AST 40    // A smem row stride (bf16 units)
#define BST 136   // B smem row stride (bf16 units)

__global__ void __launch_bounds__(256, 2)
gemm_mma_kernel(const float* __restrict__ A, float* __restrict__ C, int M)
{
    __shared__ __align__(16) char sA1[BM * AST * 2];
    __shared__ __align__(16) char sA2[BM * AST * 2];
    __shared__ __align__(16) char sB1[BK * BST * 2];
    __shared__ __align__(16) char sB2[BK * BST * 2];

    const int tid  = threadIdx.x;
    const int wid  = tid >> 5;
    const int lane = tid & 31;
    const int m0 = blockIdx.x * BM;
    const int n0 = blockIdx.y * BN;

    const int wm = (wid & 1) * 64;
    const int wn = (wid >> 1) * 32;

    float acc[4][4][4];
#pragma unroll
    for (int i = 0; i < 4; i++)
#pragma unroll
        for (int j = 0; j < 4; j++)
#pragma unroll
            for (int r = 0; r < 4; r++) acc[i][j][r] = 0.f;

    const int a_row  = tid >> 1;
    const int a_colb = (tid & 1) * 16;
    const int a_gr   = m0 + a_row;
    const int b_kr  = tid >> 3;            // 0..31
    const int b_nb  = (tid & 7) * 16;      // 0..112 (16 bf16 = 2 uint4)

    const int mat  = lane >> 3;
    const int l8   = lane & 7;
    const int a_mrow = (mat & 1) * 8 + l8;
    const int a_koff = (mat >> 1) * 8;
    const int b_krow = (mat & 1) * 8 + l8;
    const int b_noff = (mat >> 1) * 8;

    const uint32_t sa1 = smem_u32(sA1), sa2 = smem_u32(sA2);
    const uint32_t sb1 = smem_u32(sB1), sb2 = smem_u32(sB2);

    float4 va[4];
    uint4 vbh[2], vbl[2];
    // prologue: chunk 0
    {
        if (a_gr < M) {
            const float4* p = (const float4*)(A + (size_t)a_gr * IND + a_colb);
#pragma unroll
            for (int q = 0; q < 4; q++) va[q] = p[q];
        } else {
#pragma unroll
            for (int q = 0; q < 4; q++) va[q] = make_float4(0, 0, 0, 0);
        }
        const uint4* p1 = (const uint4*)(g_B1 + (size_t)b_kr * HF + n0 + b_nb);
        const uint4* p2 = (const uint4*)(g_B2 + (size_t)b_kr * HF + n0 + b_nb);
        vbh[0] = p1[0]; vbh[1] = p1[1];
        vbl[0] = p2[0]; vbl[1] = p2[1];
    }

    for (int c = 0; c < IND / BK; c++) {
        // convert/store current chunk
        {
            uint32_t hi[8], lo[8];
#pragma unroll
            for (int q = 0; q < 4; q++) {
                hi[2 * q]     = pack_hi(va[q].x, va[q].y);
                hi[2 * q + 1] = pack_hi(va[q].z, va[q].w);
                lo[2 * q]     = pack_lo(va[q].x, va[q].y);
                lo[2 * q + 1] = pack_lo(va[q].z, va[q].w);
            }
            char* d1 = sA1 + (a_row * AST + a_colb) * 2;
            char* d2 = sA2 + (a_row * AST + a_colb) * 2;
            ((uint4*)d1)[0] = make_uint4(hi[0], hi[1], hi[2], hi[3]);
            ((uint4*)d1)[1] = make_uint4(hi[4], hi[5], hi[6], hi[7]);
            ((uint4*)d2)[0] = make_uint4(lo[0], lo[1], lo[2], lo[3]);
            ((uint4*)d2)[1] = make_uint4(lo[4], lo[5], lo[6], lo[7]);
            char* e1 = sB1 + (b_kr * BST + b_nb) * 2;
            char* e2 = sB2 + (b_kr * BST + b_nb) * 2;
            ((uint4*)e1)[0] = vbh[0];
            ((uint4*)e1)[1] = vbh[1];
            ((uint4*)e2)[0] = vbl[0];
            ((uint4*)e2)[1] = vbl[1];
        }
        __syncthreads();

        // prefetch next chunk (overlaps MMA)
        if (c + 1 < IND / BK) {
            const int k0 = (c + 1) * BK;
            if (a_gr < M) {
                const float4* p = (const float4*)(A + (size_t)a_gr * IND + k0 + a_colb);
#pragma unroll
                for (int q = 0; q < 4; q++) va[q] = p[q];
            } else {
#pragma unroll
                for (int q = 0; q < 4; q++) va[q] = make_float4(0, 0, 0, 0);
            }
            const uint4* p1 = (const uint4*)(g_B1 + (size_t)(k0 + b_kr) * HF + n0 + b_nb);
            const uint4* p2 = (const uint4*)(g_B2 + (size_t)(k0 + b_kr) * HF + n0 + b_nb);
            vbh[0] = p1[0]; vbh[1] = p1[1];
            vbl[0] = p2[0]; vbl[1] = p2[1];
        }

        // MMA over current smem
#pragma unroll
        for (int kk = 0; kk < 2; kk++) {
            uint32_t a1[4][4], a2[4][4], b1[2][4], b2[2][4];
#pragma unroll
            for (int i = 0; i < 4; i++) {
                uint32_t off = ((wm + i * 16 + a_mrow) * AST + kk * 16 + a_koff) * 2;
                ldmatrix_x4(a1[i], sa1 + off);
                ldmatrix_x4(a2[i], sa2 + off);
            }
#pragma unroll
            for (int j2 = 0; j2 < 2; j2++) {
                uint32_t off = ((kk * 16 + b_krow) * BST + wn + j2 * 16 + b_noff) * 2;
                ldmatrix_x4_t(b1[j2], sb1 + off);
                ldmatrix_x4_t(b2[j2], sb2 + off);
            }
#pragma unroll
            for (int i = 0; i < 4; i++) {
#pragma unroll
                for (int j2 = 0; j2 < 2; j2++) {
                    mma_bf16(acc[i][2 * j2],     a1[i], b1[j2][0], b1[j2][1]);
                    mma_bf16(acc[i][2 * j2],     a1[i], b2[j2][0], b2[j2][1]);
                    mma_bf16(acc[i][2 * j2],     a2[i], b1[j2][0], b1[j2][1]);
                    mma_bf16(acc[i][2 * j2 + 1], a1[i], b1[j2][2], b1[j2][3]);
                    mma_bf16(acc[i][2 * j2 + 1], a1[i], b2[j2][2], b2[j2][3]);
                    mma_bf16(acc[i][2 * j2 + 1], a2[i], b1[j2][2], b1[j2][3]);
                }
            }
        }
        __syncthreads();
    }

    const int crow = lane >> 2;
    const int ccol = (lane & 3) * 2;
#pragma unroll
    for (int i = 0; i < 4; i++) {
        int r0 = m0 + wm + i * 16 + crow;
#pragma unroll
        for (int j = 0; j < 4; j++) {
            int c = n0 + wn + j * 8 + ccol;
            if (r0 < M)
                *(float2*)(C + (size_t)r0 * HF + c) = make_float2(acc[i][j][0], acc[i][j][1]);
            if (r0 + 8 < M)
                *(float2*)(C + (size_t)(r0 + 8) * HF + c) = make_float2(acc[i][j][2], acc[i][j][3]);
        }
    }
}

// ---------------- el / er: warp per node -------------------------------------
__global__ void elr_kernel(const float* __restrict__ attn_l,
                           const float* __restrict__ attn_r)
{
    int w = (blockIdx.x * blockDim.x + threadIdx.x) >> 5;
    int lane = threadIdx.x & 31;
    if (w >= NN) return;
    const float4* fp = (const float4*)(g_feat + (size_t)w * HF + lane * 8);
    float4 v0 = fp[0], v1 = fp[1];
    const float4* alp = (const float4*)(attn_l + lane * 8);
    const float4* arp = (const float4*)(attn_r + lane * 8);
    float4 a0 = alp[0], a1 = alp[1], b0 = arp[0], b1 = arp[1];
    float sl = v0.x * a0.x + v0.y * a0.y + v0.z * a0.z + v0.w * a0.w
             + v1.x * a1.x + v1.y * a1.y + v1.z * a1.z + v1.w * a1.w;
    float sr = v0.x * b0.x + v0.y * b0.y + v0.z * b0.z + v0.w * b0.w
             + v1.x * b1.x + v1.y * b1.y + v1.z * b1.z + v1.w * b1.w;
#pragma unroll
    for (int o = 4; o >= 1; o >>= 1) {
        sl += __shfl_xor_sync(0xffffffffu, sl, o);
        sr += __shfl_xor_sync(0xffffffffu, sr, o);
    }
    if ((lane & 7) == 0) {
        int h = lane >> 3;
        g_el[w * HH + h] = sl;
        g_er[w * HH + h] = sr;
    }
}

// ---------------- ee per etype ------------------------------------------------
__global__ void ee_kernel(const float* __restrict__ edge_emb,
                          const float* __restrict__ fc_e_w,
                          const float* __restrict__ attn_e)
{
    int t = threadIdx.x;
    if (t >= NT * HH) return;
    int tt = t >> 2, h = t & 3;
    float sum = 0.f;
    for (int e = 0; e < EFD; e++) {
        float ef = 0.f;
#pragma unroll 8
        for (int k = 0; k < EFD; k++)
            ef += edge_emb[tt * EFD + k] * fc_e_w[k * (HH * EFD) + h * EFD + e];
        sum += ef * attn_e[h * EFD + e];
    }
    g_ee[tt * HH + h] = sum;
}

// ---------------- CSR build ---------------------------------------------------
__global__ void zero_kernel()
{
    int i = blockIdx.x * blockDim.x + threadIdx.x;
    if (i < NN * HH) g_sum[i] = 0.f;
    if (i <= NN) g_cnt[i] = 0;
}

__global__ void count_kernel(const int* __restrict__ dst)
{
    int e = blockIdx.x * blockDim.x + threadIdx.x;
    if (e < EE) atomicAdd(&g_cnt[dst[e]], 1);
}

#define SCAN_B 1024
#define NSCAN ((NN + SCAN_B - 1) / SCAN_B)

__global__ void scan1_kernel()
{
    __shared__ int s[SCAN_B];
    int b = blockIdx.x, tid = threadIdx.x;
    int idx = b * SCAN_B + tid;
    int v = (idx < NN) ? g_cnt[idx] : 0;
    s[tid] = v;
    __syncthreads();
    for (int off = 1; off < SCAN_B; off <<= 1) {
        int tmp = (tid >= off) ? s[tid - off] : 0;
        __syncthreads();
        s[tid] += tmp;
        __syncthreads();
    }
    if (idx < NN) g_off[idx] = s[tid] - v;
    if (tid == SCAN_B - 1) g_bsum[b] = s[tid];
}

__global__ void scan2_kernel()
{
    if (threadIdx.x == 0) {
        int acc = 0;
        for (int b = 0; b < NSCAN; b++) { g_bpre[b] = acc; acc += g_bsum[b]; }
        g_bpre[NSCAN] = acc;
    }
}

__global__ void scan3_kernel()
{
    int idx = blockIdx.x * blockDim.x + threadIdx.x;
    if (idx < NN) {
        int v = g_off[idx] + g_bpre[idx >> 10];
        g_off[idx] = v;
        g_cursor[idx] = v;
    } else if (idx == NN) {
        g_off[NN] = g_bpre[NSCAN];
    }
}

// ---- scatter + score + exp + per-(dst,head) sum ------------------------------
__global__ void scatter_score_kernel(const int* __restrict__ src,
                                     const int* __restrict__ dst,
                                     const int* __restrict__ etype)
{
    int e = blockIdx.x * blockDim.x + threadIdx.x;
    if (e >= EE) return;
    int dv = dst[e];
    int pos = atomicAdd(&g_cursor[dv], 1);
    g_eids[pos] = e;
    int sv = src[e], tp = etype[e];
    g_srcs[pos] = sv;
    float4 l = *(const float4*)&g_el[sv * HH];
    float4 r = *(const float4*)&g_er[dv * HH];
    float4 t = *(const float4*)&g_ee[tp * HH];
    float x0 = l.x + r.x + t.x;  x0 = x0 > 0.f ? x0 : SLOPE * x0;
    float x1 = l.y + r.y + t.y;  x1 = x1 > 0.f ? x1 : SLOPE * x1;
    float x2 = l.z + r.z + t.z;  x2 = x2 > 0.f ? x2 : SLOPE * x2;
    float x3 = l.w + r.w + t.w;  x3 = x3 > 0.f ? x3 : SLOPE * x3;
    float p0 = __expf(x0), p1 = __expf(x1), p2 = __expf(x2), p3 = __expf(x3);
    *(float4*)&g_score[(size_t)pos * HH] = make_float4(p0, p1, p2, p3);
    atomicAdd(&g_sum[dv * HH + 0], p0);
    atomicAdd(&g_sum[dv * HH + 1], p1);
    atomicAdd(&g_sum[dv * HH + 2], p2);
    atomicAdd(&g_sum[dv * HH + 3], p3);
}

// ---------------- single-pass weighted aggregation ----------------------------
__global__ void __launch_bounds__(256)
aggregate_kernel(float* __restrict__ out_rst, float* __restrict__ out_a)
{
    const int d   = blockIdx.x;
    const int tid = threadIdx.x;
    const int off = g_off[d];
    const int deg = g_off[d + 1] - off;

    if (deg == 0) { out_rst[(size_t)d * HF + tid] = 0.f; return; }

    __shared__ float Sh[HH];
    __shared__ float w_sh[64 * HH];
    __shared__ int   src_sh[64];

    if (tid < HH) Sh[tid] = 1.f / g_sum[d * HH + tid];
    __syncthreads();

    const int h = tid & 3;
    const int g = tid >> 2;
    const int hh = tid >> 6;
    float acc = 0.f;

    for (int base = 0; base < deg; base += 64) {
        int cnt = min(64, deg - base);
        if (tid < cnt * HH) {
            // contiguous: g_score[(off+base)*4 + tid]
            float p = g_score[(size_t)(off + base) * HH + tid];
            float w = p * Sh[h];
            w_sh[tid] = w;
            int e = g_eids[off + base + g];
            out_a[(size_t)e * HH + h] = w;
            if (h == 0) src_sh[g] = g_srcs[off + base + g];
        }
        __syncthreads();
#pragma unroll 4
        for (int i = 0; i < cnt; i++) {
            acc += w_sh[i * HH + hh] * __ldg(&g_feat[(size_t)src_sh[i] * HF + tid]);
        }
        __syncthreads();
    }
    out_rst[(size_t)d * HF + tid] = acc;
}

// ---------------- launch ------------------------------------------------------
extern "C" void kernel_launch(void* const* d_in, const int* in_sizes, int n_in,
                              void* d_out, int out_size)
{
    const float* nfeat    = (const float*)d_in[0];
    const float* fc_w     = (const float*)d_in[1];
    const float* fc_e_w   = (const float*)d_in[2];
    const float* attn_l   = (const float*)d_in[3];
    const float* attn_r   = (const float*)d_in[4];
    const float* attn_e   = (const float*)d_in[5];
    const float* edge_emb = (const float*)d_in[6];
    const int*   src      = (const int*)d_in[7];
    const int*   dst      = (const int*)d_in[8];
    const int*   etype    = (const int*)d_in[9];

    float* out_rst = (float*)d_out;
    float* out_a   = (float*)d_out + (size_t)NN * HF;

    float* feat_ptr;
    cudaGetSymbolAddress((void**)&feat_ptr, g_feat);

    // GEMM stays at launch index 3 (the slot ncu captures).
    zero_kernel<<<(NN * HH + 255) / 256, 256>>>();                 // 0
    count_kernel<<<(EE + 255) / 256, 256>>>(dst);                  // 1
    convert_b_kernel<<<(IND * HF / 4 + 255) / 256, 256>>>(fc_w);   // 2
    {
        dim3 grid((NN + BM - 1) / BM, HF / BN);
        gemm_mma_kernel<<<grid, 256>>>(nfeat, feat_ptr, NN);       // 3  <- profiled
    }
    scan1_kernel<<<NSCAN, SCAN_B>>>();                             // 4
    ee_kernel<<<1, 32>>>(edge_emb, fc_e_w, attn_e);                // 5
    scan2_kernel<<<1, 32>>>();                                     // 6
    scan3_kernel<<<(NN + 256) / 256, 256>>>();                     // 7
    elr_kernel<<<(NN * 32 + 255) / 256, 256>>>(attn_l, attn_r);    // 8
    scatter_score_kernel<<<(EE + 255) / 256, 256>>>(src, dst, etype); // 9
    aggregate_kernel<<<NN, 256>>>(out_rst, out_a);                 // 10
}

// round 6
// speedup vs baseline: 1.5607x; 1.0677x over previous
#include <cuda_runtime.h>
#include <cuda_bf16.h>
#include <math.h>
#include <stdint.h>

// Problem constants
#define NN   50000
#define EE   800000
#define IND  256
#define HH   4
#define FF   64
#define HF   256
#define EFD  64
#define NT   8
#define SLOPE 0.2f

// ---------------- scratch ----------------------------------------------------
__device__ float g_feat[NN * HF];
__device__ float g_el[NN * HH];
__device__ float g_er[NN * HH];
__device__ float g_ee[NT * HH];
__device__ float g_sum[NN * HH];              // sum of exp(score) per (dst, head)
__device__ float g_score[(size_t)EE * HH];    // exp(score), CSR order
__device__ int   g_srcs[EE];                  // src node per CSR slot
__device__ __nv_bfloat16 g_B1[IND * HF];      // fc_w hi (bf16)
__device__ __nv_bfloat16 g_B2[IND * HF];      // fc_w lo (bf16)
__device__ int   g_cnt[NN + 1];
__device__ int   g_off[NN + 1];
__device__ int   g_cursor[NN];
__device__ int   g_bsum[64];
__device__ int   g_bpre[65];

// ---------------- helpers -----------------------------------------------------
__device__ __forceinline__ uint32_t smem_u32(const void* p) {
    uint32_t a;
    asm("{ .reg .u64 t; cvta.to.shared.u64 t, %1; cvt.u32.u64 %0, t; }"
        : "=r"(a) : "l"(p));
    return a;
}
__device__ __forceinline__ void ldmatrix_x4(uint32_t* r, uint32_t addr) {
    asm volatile("ldmatrix.sync.aligned.m8n8.x4.shared.b16 {%0,%1,%2,%3}, [%4];"
                 : "=r"(r[0]), "=r"(r[1]), "=r"(r[2]), "=r"(r[3]) : "r"(addr));
}
__device__ __forceinline__ void ldmatrix_x4_t(uint32_t* r, uint32_t addr) {
    asm volatile("ldmatrix.sync.aligned.m8n8.x4.trans.shared.b16 {%0,%1,%2,%3}, [%4];"
                 : "=r"(r[0]), "=r"(r[1]), "=r"(r[2]), "=r"(r[3]) : "r"(addr));
}
__device__ __forceinline__ void mma_bf16(float* c, const uint32_t* a,
                                         uint32_t b0, uint32_t b1) {
    asm volatile(
        "mma.sync.aligned.m16n8k16.row.col.f32.bf16.bf16.f32 "
        "{%0,%1,%2,%3}, {%4,%5,%6,%7}, {%8,%9}, {%0,%1,%2,%3};"
        : "+f"(c[0]), "+f"(c[1]), "+f"(c[2]), "+f"(c[3])
        : "r"(a[0]), "r"(a[1]), "r"(a[2]), "r"(a[3]), "r"(b0), "r"(b1));
}
__device__ __forceinline__ uint32_t pack_hi(float a, float b) {
    return ((uint32_t)__bfloat16_as_ushort(__float2bfloat16_rn(b)) << 16) |
           (uint32_t)__bfloat16_as_ushort(__float2bfloat16_rn(a));
}
__device__ __forceinline__ uint32_t pack_lo(float a, float b) {
    float ar = a - __bfloat162float(__float2bfloat16_rn(a));
    float br = b - __bfloat162float(__float2bfloat16_rn(b));
    return ((uint32_t)__bfloat16_as_ushort(__float2bfloat16_rn(br)) << 16) |
           (uint32_t)__bfloat16_as_ushort(__float2bfloat16_rn(ar));
}

// ---------------- B pre-conversion to bf16 hi/lo ------------------------------
__global__ void convert_b_kernel(const float* __restrict__ Bw)
{
    int i = (blockIdx.x * blockDim.x + threadIdx.x) * 4;
    float4 v = *(const float4*)(Bw + i);
    float f[4] = { v.x, v.y, v.z, v.w };
#pragma unroll
    for (int q = 0; q < 4; q++) {
        __nv_bfloat16 h = __float2bfloat16_rn(f[q]);
        g_B1[i + q] = h;
        g_B2[i + q] = __float2bfloat16_rn(f[q] - __bfloat162float(h));
    }
}

// ---------------- bf16-split GEMM via mma.sync, fused el/er epilogue ----------
#define BM 128
#define BN 128
#define BK 32
#define AST 40    // A smem row stride (bf16 units)
#define BST 136   // B smem row stride (bf16 units)

__global__ void __launch_bounds__(256, 2)
gemm_mma_kernel(const float* __restrict__ A, float* __restrict__ C,
                const float* __restrict__ attn_l, const float* __restrict__ attn_r,
                int M)
{
    __shared__ __align__(16) char sA1[BM * AST * 2];
    __shared__ __align__(16) char sA2[BM * AST * 2];
    __shared__ __align__(16) char sB1[BK * BST * 2];
    __shared__ __align__(16) char sB2[BK * BST * 2];

    const int tid  = threadIdx.x;
    const int wid  = tid >> 5;
    const int lane = tid & 31;
    const int m0 = blockIdx.x * BM;
    const int n0 = blockIdx.y * BN;

    const int wm = (wid & 1) * 64;
    const int wn = (wid >> 1) * 32;

    float acc[4][4][4];
#pragma unroll
    for (int i = 0; i < 4; i++)
#pragma unroll
        for (int j = 0; j < 4; j++)
#pragma unroll
            for (int r = 0; r < 4; r++) acc[i][j][r] = 0.f;

    const int a_row  = tid >> 1;
    const int a_colb = (tid & 1) * 16;
    const int a_gr   = m0 + a_row;
    const int b_kr  = tid >> 3;
    const int b_nb  = (tid & 7) * 16;

    const int mat  = lane >> 3;
    const int l8   = lane & 7;
    const int a_mrow = (mat & 1) * 8 + l8;
    const int a_koff = (mat >> 1) * 8;
    const int b_krow = (mat & 1) * 8 + l8;
    const int b_noff = (mat >> 1) * 8;

    const uint32_t sa1 = smem_u32(sA1), sa2 = smem_u32(sA2);
    const uint32_t sb1 = smem_u32(sB1), sb2 = smem_u32(sB2);

    float4 va[4];
    uint4 vbh[2], vbl[2];
    {
        if (a_gr < M) {
            const float4* p = (const float4*)(A + (size_t)a_gr * IND + a_colb);
#pragma unroll
            for (int q = 0; q < 4; q++) va[q] = p[q];
        } else {
#pragma unroll
            for (int q = 0; q < 4; q++) va[q] = make_float4(0, 0, 0, 0);
        }
        const uint4* p1 = (const uint4*)(g_B1 + (size_t)b_kr * HF + n0 + b_nb);
        const uint4* p2 = (const uint4*)(g_B2 + (size_t)b_kr * HF + n0 + b_nb);
        vbh[0] = p1[0]; vbh[1] = p1[1];
        vbl[0] = p2[0]; vbl[1] = p2[1];
    }

    for (int c = 0; c < IND / BK; c++) {
        {
            uint32_t hi[8], lo[8];
#pragma unroll
            for (int q = 0; q < 4; q++) {
                hi[2 * q]     = pack_hi(va[q].x, va[q].y);
                hi[2 * q + 1] = pack_hi(va[q].z, va[q].w);
                lo[2 * q]     = pack_lo(va[q].x, va[q].y);
                lo[2 * q + 1] = pack_lo(va[q].z, va[q].w);
            }
            char* d1 = sA1 + (a_row * AST + a_colb) * 2;
            char* d2 = sA2 + (a_row * AST + a_colb) * 2;
            ((uint4*)d1)[0] = make_uint4(hi[0], hi[1], hi[2], hi[3]);
            ((uint4*)d1)[1] = make_uint4(hi[4], hi[5], hi[6], hi[7]);
            ((uint4*)d2)[0] = make_uint4(lo[0], lo[1], lo[2], lo[3]);
            ((uint4*)d2)[1] = make_uint4(lo[4], lo[5], lo[6], lo[7]);
            char* e1 = sB1 + (b_kr * BST + b_nb) * 2;
            char* e2 = sB2 + (b_kr * BST + b_nb) * 2;
            ((uint4*)e1)[0] = vbh[0];
            ((uint4*)e1)[1] = vbh[1];
            ((uint4*)e2)[0] = vbl[0];
            ((uint4*)e2)[1] = vbl[1];
        }
        __syncthreads();

        if (c + 1 < IND / BK) {
            const int k0 = (c + 1) * BK;
            if (a_gr < M) {
                const float4* p = (const float4*)(A + (size_t)a_gr * IND + k0 + a_colb);
#pragma unroll
                for (int q = 0; q < 4; q++) va[q] = p[q];
            } else {
#pragma unroll
                for (int q = 0; q < 4; q++) va[q] = make_float4(0, 0, 0, 0);
            }
            const uint4* p1 = (const uint4*)(g_B1 + (size_t)(k0 + b_kr) * HF + n0 + b_nb);
            const uint4* p2 = (const uint4*)(g_B2 + (size_t)(k0 + b_kr) * HF + n0 + b_nb);
            vbh[0] = p1[0]; vbh[1] = p1[1];
            vbl[0] = p2[0]; vbl[1] = p2[1];
        }

#pragma unroll
        for (int kk = 0; kk < 2; kk++) {
            uint32_t a1[4][4], a2[4][4], b1[2][4], b2[2][4];
#pragma unroll
            for (int i = 0; i < 4; i++) {
                uint32_t off = ((wm + i * 16 + a_mrow) * AST + kk * 16 + a_koff) * 2;
                ldmatrix_x4(a1[i], sa1 + off);
                ldmatrix_x4(a2[i], sa2 + off);
            }
#pragma unroll
            for (int j2 = 0; j2 < 2; j2++) {
                uint32_t off = ((kk * 16 + b_krow) * BST + wn + j2 * 16 + b_noff) * 2;
                ldmatrix_x4_t(b1[j2], sb1 + off);
                ldmatrix_x4_t(b2[j2], sb2 + off);
            }
#pragma unroll
            for (int i = 0; i < 4; i++) {
#pragma unroll
                for (int j2 = 0; j2 < 2; j2++) {
                    mma_bf16(acc[i][2 * j2],     a1[i], b1[j2][0], b1[j2][1]);
                    mma_bf16(acc[i][2 * j2],     a1[i], b2[j2][0], b2[j2][1]);
                    mma_bf16(acc[i][2 * j2],     a2[i], b1[j2][0], b1[j2][1]);
                    mma_bf16(acc[i][2 * j2 + 1], a1[i], b1[j2][2], b1[j2][3]);
                    mma_bf16(acc[i][2 * j2 + 1], a1[i], b2[j2][2], b2[j2][3]);
                    mma_bf16(acc[i][2 * j2 + 1], a2[i], b1[j2][2], b1[j2][3]);
                }
            }
        }
        __syncthreads();
    }

    // ---- epilogue: store C + fused el/er partial reduction
    const int crow = lane >> 2;
    const int ccol = (lane & 3) * 2;

    float al[4][2], ar[4][2];
#pragma unroll
    for (int j = 0; j < 4; j++) {
        int c = n0 + wn + j * 8 + ccol;
        al[j][0] = attn_l[c];     al[j][1] = attn_l[c + 1];
        ar[j][0] = attn_r[c];     ar[j][1] = attn_r[c + 1];
    }
    const int head = (n0 + wn) >> 6;

#pragma unroll
    for (int i = 0; i < 4; i++) {
        int r0 = m0 + wm + i * 16 + crow;
        float pl0 = 0.f, pr0 = 0.f, pl1 = 0.f, pr1 = 0.f;
#pragma unroll
        for (int j = 0; j < 4; j++) {
            int c = n0 + wn + j * 8 + ccol;
            if (r0 < M)
                *(float2*)(C + (size_t)r0 * HF + c) = make_float2(acc[i][j][0], acc[i][j][1]);
            if (r0 + 8 < M)
                *(float2*)(C + (size_t)(r0 + 8) * HF + c) = make_float2(acc[i][j][2], acc[i][j][3]);
            pl0 += acc[i][j][0] * al[j][0] + acc[i][j][1] * al[j][1];
            pr0 += acc[i][j][0] * ar[j][0] + acc[i][j][1] * ar[j][1];
            pl1 += acc[i][j][2] * al[j][0] + acc[i][j][3] * al[j][1];
            pr1 += acc[i][j][2] * ar[j][0] + acc[i][j][3] * ar[j][1];
        }
        // quad reduce (lanes sharing the same row)
#pragma unroll
        for (int o = 1; o <= 2; o <<= 1) {
            pl0 += __shfl_xor_sync(0xffffffffu, pl0, o);
            pr0 += __shfl_xor_sync(0xffffffffu, pr0, o);
            pl1 += __shfl_xor_sync(0xffffffffu, pl1, o);
            pr1 += __shfl_xor_sync(0xffffffffu, pr1, o);
        }
        if ((lane & 3) == 0) {
            if (r0 < M) {
                atomicAdd(&g_el[r0 * HH + head], pl0);
                atomicAdd(&g_er[r0 * HH + head], pr0);
            }
            if (r0 + 8 < M) {
                atomicAdd(&g_el[(r0 + 8) * HH + head], pl1);
                atomicAdd(&g_er[(r0 + 8) * HH + head], pr1);
            }
        }
    }
}

// ---------------- ee per etype ------------------------------------------------
__global__ void ee_kernel(const float* __restrict__ edge_emb,
                          const float* __restrict__ fc_e_w,
                          const float* __restrict__ attn_e)
{
    int t = threadIdx.x;
    if (t >= NT * HH) return;
    int tt = t >> 2, h = t & 3;
    float sum = 0.f;
    for (int e = 0; e < EFD; e++) {
        float ef = 0.f;
#pragma unroll 8
        for (int k = 0; k < EFD; k++)
            ef += edge_emb[tt * EFD + k] * fc_e_w[k * (HH * EFD) + h * EFD + e];
        sum += ef * attn_e[h * EFD + e];
    }
    g_ee[tt * HH + h] = sum;
}

// ---------------- zero + CSR build --------------------------------------------
__global__ void zero_kernel()
{
    int i = blockIdx.x * blockDim.x + threadIdx.x;
    if (i < NN * HH) { g_sum[i] = 0.f; g_el[i] = 0.f; g_er[i] = 0.f; }
    if (i <= NN) g_cnt[i] = 0;
}

__global__ void count_kernel(const int* __restrict__ dst)
{
    int e = blockIdx.x * blockDim.x + threadIdx.x;
    if (e < EE) atomicAdd(&g_cnt[dst[e]], 1);
}

#define SCAN_B 1024
#define NSCAN ((NN + SCAN_B - 1) / SCAN_B)

__global__ void scan1_kernel()
{
    __shared__ int s[SCAN_B];
    int b = blockIdx.x, tid = threadIdx.x;
    int idx = b * SCAN_B + tid;
    int v = (idx < NN) ? g_cnt[idx] : 0;
    s[tid] = v;
    __syncthreads();
    for (int off = 1; off < SCAN_B; off <<= 1) {
        int tmp = (tid >= off) ? s[tid - off] : 0;
        __syncthreads();
        s[tid] += tmp;
        __syncthreads();
    }
    if (idx < NN) g_off[idx] = s[tid] - v;
    if (tid == SCAN_B - 1) g_bsum[b] = s[tid];
}

__global__ void scan2_kernel()
{
    if (threadIdx.x == 0) {
        int acc = 0;
        for (int b = 0; b < NSCAN; b++) { g_bpre[b] = acc; acc += g_bsum[b]; }
        g_bpre[NSCAN] = acc;
    }
}

__global__ void scan3_kernel()
{
    int idx = blockIdx.x * blockDim.x + threadIdx.x;
    if (idx < NN) {
        int v = g_off[idx] + g_bpre[idx >> 10];
        g_off[idx] = v;
        g_cursor[idx] = v;
    } else if (idx == NN) {
        g_off[NN] = g_bpre[NSCAN];
    }
}

// ---- scatter: CSR order srcs + exp(score) + per-(dst,head) sums --------------
__global__ void scatter_score_kernel(const int* __restrict__ src,
                                     const int* __restrict__ dst,
                                     const int* __restrict__ etype)
{
    int e = blockIdx.x * blockDim.x + threadIdx.x;
    if (e >= EE) return;
    int dv = dst[e];
    int pos = atomicAdd(&g_cursor[dv], 1);
    int sv = src[e], tp = etype[e];
    g_srcs[pos] = sv;
    float4 l = *(const float4*)&g_el[sv * HH];
    float4 r = *(const float4*)&g_er[dv * HH];
    float4 t = *(const float4*)&g_ee[tp * HH];
    float x0 = l.x + r.x + t.x;  x0 = x0 > 0.f ? x0 : SLOPE * x0;
    float x1 = l.y + r.y + t.y;  x1 = x1 > 0.f ? x1 : SLOPE * x1;
    float x2 = l.z + r.z + t.z;  x2 = x2 > 0.f ? x2 : SLOPE * x2;
    float x3 = l.w + r.w + t.w;  x3 = x3 > 0.f ? x3 : SLOPE * x3;
    float p0 = __expf(x0), p1 = __expf(x1), p2 = __expf(x2), p3 = __expf(x3);
    *(float4*)&g_score[(size_t)pos * HH] = make_float4(p0, p1, p2, p3);
    atomicAdd(&g_sum[dv * HH + 0], p0);
    atomicAdd(&g_sum[dv * HH + 1], p1);
    atomicAdd(&g_sum[dv * HH + 2], p2);
    atomicAdd(&g_sum[dv * HH + 3], p3);
}

// ---- out_a: edge-parallel, original edge order, fully coalesced writes -------
__global__ void out_a_kernel(const int* __restrict__ src,
                             const int* __restrict__ dst,
                             const int* __restrict__ etype,
                             float* __restrict__ out_a)
{
    int e = blockIdx.x * blockDim.x + threadIdx.x;
    if (e >= EE) return;
    int sv = src[e], dv = dst[e], tp = etype[e];
    float4 l = *(const float4*)&g_el[sv * HH];
    float4 r = *(const float4*)&g_er[dv * HH];
    float4 t = *(const float4*)&g_ee[tp * HH];
    float4 s = *(const float4*)&g_sum[dv * HH];
    float x0 = l.x + r.x + t.x;  x0 = x0 > 0.f ? x0 : SLOPE * x0;
    float x1 = l.y + r.y + t.y;  x1 = x1 > 0.f ? x1 : SLOPE * x1;
    float x2 = l.z + r.z + t.z;  x2 = x2 > 0.f ? x2 : SLOPE * x2;
    float x3 = l.w + r.w + t.w;  x3 = x3 > 0.f ? x3 : SLOPE * x3;
    float4 w;
    w.x = __expf(x0) * (1.f / s.x);
    w.y = __expf(x1) * (1.f / s.y);
    w.z = __expf(x2) * (1.f / s.z);
    w.w = __expf(x3) * (1.f / s.w);
    *(float4*)&out_a[(size_t)e * HH] = w;
}

// ---------------- weighted aggregation (rst only) -----------------------------
__global__ void __launch_bounds__(256)
aggregate_kernel(float* __restrict__ out_rst)
{
    const int d   = blockIdx.x;
    const int tid = threadIdx.x;
    const int off = g_off[d];
    const int deg = g_off[d + 1] - off;

    if (deg == 0) { out_rst[(size_t)d * HF + tid] = 0.f; return; }

    __shared__ float Sh[HH];
    __shared__ float w_sh[64 * HH];
    __shared__ int   src_sh[64];

    if (tid < HH) Sh[tid] = 1.f / g_sum[d * HH + tid];
    __syncthreads();

    const int h = tid & 3;
    const int g = tid >> 2;
    const int hh = tid >> 6;
    float acc = 0.f;

    for (int base = 0; base < deg; base += 64) {
        int cnt = min(64, deg - base);
        if (tid < cnt * HH) {
            float p = g_score[(size_t)(off + base) * HH + tid];
            w_sh[tid] = p * Sh[h];
            if (h == 0) src_sh[g] = g_srcs[off + base + g];
        }
        __syncthreads();
#pragma unroll 4
        for (int i = 0; i < cnt; i++) {
            acc += w_sh[i * HH + hh] * __ldg(&g_feat[(size_t)src_sh[i] * HF + tid]);
        }
        __syncthreads();
    }
    out_rst[(size_t)d * HF + tid] = acc;
}

// ---------------- launch ------------------------------------------------------
extern "C" void kernel_launch(void* const* d_in, const int* in_sizes, int n_in,
                              void* d_out, int out_size)
{
    const float* nfeat    = (const float*)d_in[0];
    const float* fc_w     = (const float*)d_in[1];
    const float* fc_e_w   = (const float*)d_in[2];
    const float* attn_l   = (const float*)d_in[3];
    const float* attn_r   = (const float*)d_in[4];
    const float* attn_e   = (const float*)d_in[5];
    const float* edge_emb = (const float*)d_in[6];
    const int*   src      = (const int*)d_in[7];
    const int*   dst      = (const int*)d_in[8];
    const int*   etype    = (const int*)d_in[9];

    float* out_rst = (float*)d_out;
    float* out_a   = (float*)d_out + (size_t)NN * HF;

    float* feat_ptr;
    cudaGetSymbolAddress((void**)&feat_ptr, g_feat);

    // GEMM stays at launch index 3 (the slot ncu captures).
    zero_kernel<<<(NN * HH + 255) / 256, 256>>>();                 // 0
    count_kernel<<<(EE + 255) / 256, 256>>>(dst);                  // 1
    convert_b_kernel<<<(IND * HF / 4 + 255) / 256, 256>>>(fc_w);   // 2
    {
        dim3 grid((NN + BM - 1) / BM, HF / BN);
        gemm_mma_kernel<<<grid, 256>>>(nfeat, feat_ptr, attn_l, attn_r, NN); // 3 <- profiled
    }
    scan1_kernel<<<NSCAN, SCAN_B>>>();                             // 4
    ee_kernel<<<1, 32>>>(edge_emb, fc_e_w, attn_e);                // 5
    scan2_kernel<<<1, 32>>>();                                     // 6
    scan3_kernel<<<(NN + 256) / 256, 256>>>();                     // 7
    scatter_score_kernel<<<(EE + 255) / 256, 256>>>(src, dst, etype); // 8
    out_a_kernel<<<(EE + 255) / 256, 256>>>(src, dst, etype, out_a);  // 9
    aggregate_kernel<<<NN, 256>>>(out_rst);                        // 10
}

// round 7
// speedup vs baseline: 1.6448x; 1.0539x over previous
#include <cuda_runtime.h>
#include <cuda_bf16.h>
#include <math.h>
#include <stdint.h>

// Problem constants
#define NN   50000
#define EE   800000
#define IND  256
#define HH   4
#define FF   64
#define HF   256
#define EFD  64
#define NT   8
#define SLOPE 0.2f

// ---------------- scratch ----------------------------------------------------
__device__ float g_feat[NN * HF];
__device__ float g_el[NN * HH];
__device__ float g_er[NN * HH];
__device__ float g_ee[NT * HH];
__device__ float g_sum[NN * HH];
__device__ float g_score[(size_t)EE * HH];    // exp(score), CSR order
__device__ int   g_srcs[EE];                  // src node per CSR slot
__device__ __nv_bfloat16 g_B1[IND * HF];
__device__ __nv_bfloat16 g_B2[IND * HF];
__device__ int   g_cnt[NN + 1];
__device__ int   g_off[NN + 1];
__device__ int   g_cursor[NN];
__device__ int   g_bsum[64];
__device__ int   g_bpre[65];

// ---------------- helpers -----------------------------------------------------
__device__ __forceinline__ uint32_t smem_u32(const void* p) {
    uint32_t a;
    asm("{ .reg .u64 t; cvta.to.shared.u64 t, %1; cvt.u32.u64 %0, t; }"
        : "=r"(a) : "l"(p));
    return a;
}
__device__ __forceinline__ void ldmatrix_x4(uint32_t* r, uint32_t addr) {
    asm volatile("ldmatrix.sync.aligned.m8n8.x4.shared.b16 {%0,%1,%2,%3}, [%4];"
                 : "=r"(r[0]), "=r"(r[1]), "=r"(r[2]), "=r"(r[3]) : "r"(addr));
}
__device__ __forceinline__ void ldmatrix_x4_t(uint32_t* r, uint32_t addr) {
    asm volatile("ldmatrix.sync.aligned.m8n8.x4.trans.shared.b16 {%0,%1,%2,%3}, [%4];"
                 : "=r"(r[0]), "=r"(r[1]), "=r"(r[2]), "=r"(r[3]) : "r"(addr));
}
__device__ __forceinline__ void mma_bf16(float* c, const uint32_t* a,
                                         uint32_t b0, uint32_t b1) {
    asm volatile(
        "mma.sync.aligned.m16n8k16.row.col.f32.bf16.bf16.f32 "
        "{%0,%1,%2,%3}, {%4,%5,%6,%7}, {%8,%9}, {%0,%1,%2,%3};"
        : "+f"(c[0]), "+f"(c[1]), "+f"(c[2]), "+f"(c[3])
        : "r"(a[0]), "r"(a[1]), "r"(a[2]), "r"(a[3]), "r"(b0), "r"(b1));
}
__device__ __forceinline__ uint32_t pack_hi(float a, float b) {
    return ((uint32_t)__bfloat16_as_ushort(__float2bfloat16_rn(b)) << 16) |
           (uint32_t)__bfloat16_as_ushort(__float2bfloat16_rn(a));
}
__device__ __forceinline__ uint32_t pack_lo(float a, float b) {
    float ar = a - __bfloat162float(__float2bfloat16_rn(a));
    float br = b - __bfloat162float(__float2bfloat16_rn(b));
    return ((uint32_t)__bfloat16_as_ushort(__float2bfloat16_rn(br)) << 16) |
           (uint32_t)__bfloat16_as_ushort(__float2bfloat16_rn(ar));
}

// ---------------- B pre-conversion ------------------------------------------
__global__ void convert_b_kernel(const float* __restrict__ Bw)
{
    int i = (blockIdx.x * blockDim.x + threadIdx.x) * 4;
    float4 v = *(const float4*)(Bw + i);
    float f[4] = { v.x, v.y, v.z, v.w };
#pragma unroll
    for (int q = 0; q < 4; q++) {
        __nv_bfloat16 h = __float2bfloat16_rn(f[q]);
        g_B1[i + q] = h;
        g_B2[i + q] = __float2bfloat16_rn(f[q] - __bfloat162float(h));
    }
}

// ---------------- bf16-split GEMM, double-buffered smem, fused el/er ---------
#define BM 128
#define BN 128
#define BK 32
#define AST 40
#define BST 136
#define STG_A1 0
#define STG_A2 10240
#define STG_B1 20480
#define STG_B2 29184
#define STG_SZ 37888
#define GEMM_SMEM (2 * STG_SZ)

__global__ void __launch_bounds__(256, 2)
gemm_mma_kernel(const float* __restrict__ A, float* __restrict__ C,
                const float* __restrict__ attn_l, const float* __restrict__ attn_r,
                int M)
{
    extern __shared__ __align__(16) char dynsm[];

    const int tid  = threadIdx.x;
    const int lane = tid & 31;
    const int wid  = tid >> 5;
    const int m0 = blockIdx.x * BM;
    const int n0 = blockIdx.y * BN;

    const int wm = (wid & 1) * 64;
    const int wn = (wid >> 1) * 32;

    float acc[4][4][4];
#pragma unroll
    for (int i = 0; i < 4; i++)
#pragma unroll
        for (int j = 0; j < 4; j++)
#pragma unroll
            for (int r = 0; r < 4; r++) acc[i][j][r] = 0.f;

    const int a_row  = tid >> 1;
    const int a_colb = (tid & 1) * 16;
    const int a_gr   = m0 + a_row;
    const int b_kr  = tid >> 3;
    const int b_nb  = (tid & 7) * 16;

    const int mat  = lane >> 3;
    const int l8   = lane & 7;
    const int a_mrow = (mat & 1) * 8 + l8;
    const int a_koff = (mat >> 1) * 8;
    const int b_krow = (mat & 1) * 8 + l8;
    const int b_noff = (mat >> 1) * 8;

    const uint32_t sm0 = smem_u32(dynsm);

    float4 va[4];
    uint4 vbh[2], vbl[2];
    {
        if (a_gr < M) {
            const float4* p = (const float4*)(A + (size_t)a_gr * IND + a_colb);
#pragma unroll
            for (int q = 0; q < 4; q++) va[q] = p[q];
        } else {
#pragma unroll
            for (int q = 0; q < 4; q++) va[q] = make_float4(0, 0, 0, 0);
        }
        const uint4* p1 = (const uint4*)(g_B1 + (size_t)b_kr * HF + n0 + b_nb);
        const uint4* p2 = (const uint4*)(g_B2 + (size_t)b_kr * HF + n0 + b_nb);
        vbh[0] = p1[0]; vbh[1] = p1[1];
        vbl[0] = p2[0]; vbl[1] = p2[1];
    }

    for (int c = 0; c < IND / BK; c++) {
        char* stg = dynsm + (c & 1) * STG_SZ;
        {
            uint32_t hi[8], lo[8];
#pragma unroll
            for (int q = 0; q < 4; q++) {
                hi[2 * q]     = pack_hi(va[q].x, va[q].y);
                hi[2 * q + 1] = pack_hi(va[q].z, va[q].w);
                lo[2 * q]     = pack_lo(va[q].x, va[q].y);
                lo[2 * q + 1] = pack_lo(va[q].z, va[q].w);
            }
            char* d1 = stg + STG_A1 + (a_row * AST + a_colb) * 2;
            char* d2 = stg + STG_A2 + (a_row * AST + a_colb) * 2;
            ((uint4*)d1)[0] = make_uint4(hi[0], hi[1], hi[2], hi[3]);
            ((uint4*)d1)[1] = make_uint4(hi[4], hi[5], hi[6], hi[7]);
            ((uint4*)d2)[0] = make_uint4(lo[0], lo[1], lo[2], lo[3]);
            ((uint4*)d2)[1] = make_uint4(lo[4], lo[5], lo[6], lo[7]);
            char* e1 = stg + STG_B1 + (b_kr * BST + b_nb) * 2;
            char* e2 = stg + STG_B2 + (b_kr * BST + b_nb) * 2;
            ((uint4*)e1)[0] = vbh[0];
            ((uint4*)e1)[1] = vbh[1];
            ((uint4*)e2)[0] = vbl[0];
            ((uint4*)e2)[1] = vbl[1];
        }
        __syncthreads();

        if (c + 1 < IND / BK) {
            const int k0 = (c + 1) * BK;
            if (a_gr < M) {
                const float4* p = (const float4*)(A + (size_t)a_gr * IND + k0 + a_colb);
#pragma unroll
                for (int q = 0; q < 4; q++) va[q] = p[q];
            } else {
#pragma unroll
                for (int q = 0; q < 4; q++) va[q] = make_float4(0, 0, 0, 0);
            }
            const uint4* p1 = (const uint4*)(g_B1 + (size_t)(k0 + b_kr) * HF + n0 + b_nb);
            const uint4* p2 = (const uint4*)(g_B2 + (size_t)(k0 + b_kr) * HF + n0 + b_nb);
            vbh[0] = p1[0]; vbh[1] = p1[1];
            vbl[0] = p2[0]; vbl[1] = p2[1];
        }

        const uint32_t sa1 = sm0 + (c & 1) * STG_SZ + STG_A1;
        const uint32_t sa2 = sm0 + (c & 1) * STG_SZ + STG_A2;
        const uint32_t sb1 = sm0 + (c & 1) * STG_SZ + STG_B1;
        const uint32_t sb2 = sm0 + (c & 1) * STG_SZ + STG_B2;

#pragma unroll
        for (int kk = 0; kk < 2; kk++) {
            uint32_t a1[4][4], a2[4][4], b1[2][4], b2[2][4];
#pragma unroll
            for (int i = 0; i < 4; i++) {
                uint32_t off = ((wm + i * 16 + a_mrow) * AST + kk * 16 + a_koff) * 2;
                ldmatrix_x4(a1[i], sa1 + off);
                ldmatrix_x4(a2[i], sa2 + off);
            }
#pragma unroll
            for (int j2 = 0; j2 < 2; j2++) {
                uint32_t off = ((kk * 16 + b_krow) * BST + wn + j2 * 16 + b_noff) * 2;
                ldmatrix_x4_t(b1[j2], sb1 + off);
                ldmatrix_x4_t(b2[j2], sb2 + off);
            }
#pragma unroll
            for (int i = 0; i < 4; i++) {
#pragma unroll
                for (int j2 = 0; j2 < 2; j2++) {
                    mma_bf16(acc[i][2 * j2],     a1[i], b1[j2][0], b1[j2][1]);
                    mma_bf16(acc[i][2 * j2],     a1[i], b2[j2][0], b2[j2][1]);
                    mma_bf16(acc[i][2 * j2],     a2[i], b1[j2][0], b1[j2][1]);
                    mma_bf16(acc[i][2 * j2 + 1], a1[i], b1[j2][2], b1[j2][3]);
                    mma_bf16(acc[i][2 * j2 + 1], a1[i], b2[j2][2], b2[j2][3]);
                    mma_bf16(acc[i][2 * j2 + 1], a2[i], b1[j2][2], b1[j2][3]);
                }
            }
        }
    }

    // ---- epilogue: store C + fused el/er
    const int crow = lane >> 2;
    const int ccol = (lane & 3) * 2;

    float al[4][2], ar[4][2];
#pragma unroll
    for (int j = 0; j < 4; j++) {
        int c = n0 + wn + j * 8 + ccol;
        al[j][0] = attn_l[c];     al[j][1] = attn_l[c + 1];
        ar[j][0] = attn_r[c];     ar[j][1] = attn_r[c + 1];
    }
    const int head = (n0 + wn) >> 6;

#pragma unroll
    for (int i = 0; i < 4; i++) {
        int r0 = m0 + wm + i * 16 + crow;
        float pl0 = 0.f, pr0 = 0.f, pl1 = 0.f, pr1 = 0.f;
#pragma unroll
        for (int j = 0; j < 4; j++) {
            int c = n0 + wn + j * 8 + ccol;
            if (r0 < M)
                *(float2*)(C + (size_t)r0 * HF + c) = make_float2(acc[i][j][0], acc[i][j][1]);
            if (r0 + 8 < M)
                *(float2*)(C + (size_t)(r0 + 8) * HF + c) = make_float2(acc[i][j][2], acc[i][j][3]);
            pl0 += acc[i][j][0] * al[j][0] + acc[i][j][1] * al[j][1];
            pr0 += acc[i][j][0] * ar[j][0] + acc[i][j][1] * ar[j][1];
            pl1 += acc[i][j][2] * al[j][0] + acc[i][j][3] * al[j][1];
            pr1 += acc[i][j][2] * ar[j][0] + acc[i][j][3] * ar[j][1];
        }
#pragma unroll
        for (int o = 1; o <= 2; o <<= 1) {
            pl0 += __shfl_xor_sync(0xffffffffu, pl0, o);
            pr0 += __shfl_xor_sync(0xffffffffu, pr0, o);
            pl1 += __shfl_xor_sync(0xffffffffu, pl1, o);
            pr1 += __shfl_xor_sync(0xffffffffu, pr1, o);
        }
        if ((lane & 3) == 0) {
            if (r0 < M) {
                atomicAdd(&g_el[r0 * HH + head], pl0);
                atomicAdd(&g_er[r0 * HH + head], pr0);
            }
            if (r0 + 8 < M) {
                atomicAdd(&g_el[(r0 + 8) * HH + head], pl1);
                atomicAdd(&g_er[(r0 + 8) * HH + head], pr1);
            }
        }
    }
}

// ---------------- ee per etype ------------------------------------------------
__global__ void ee_kernel(const float* __restrict__ edge_emb,
                          const float* __restrict__ fc_e_w,
                          const float* __restrict__ attn_e)
{
    int t = threadIdx.x;
    if (t >= NT * HH) return;
    int tt = t >> 2, h = t & 3;
    float sum = 0.f;
    for (int e = 0; e < EFD; e++) {
        float ef = 0.f;
#pragma unroll 8
        for (int k = 0; k < EFD; k++)
            ef += edge_emb[tt * EFD + k] * fc_e_w[k * (HH * EFD) + h * EFD + e];
        sum += ef * attn_e[h * EFD + e];
    }
    g_ee[tt * HH + h] = sum;
}

// ---------------- CSR build ---------------------------------------------------
__global__ void count_kernel(const int* __restrict__ dst)
{
    int e = blockIdx.x * blockDim.x + threadIdx.x;
    if (e < EE) atomicAdd(&g_cnt[dst[e]], 1);
}

#define SCAN_B 1024
#define NSCAN ((NN + SCAN_B - 1) / SCAN_B)

__global__ void scan1_kernel()
{
    __shared__ int s[SCAN_B];
    int b = blockIdx.x, tid = threadIdx.x;
    int idx = b * SCAN_B + tid;
    int v = (idx < NN) ? g_cnt[idx] : 0;
    s[tid] = v;
    __syncthreads();
    for (int off = 1; off < SCAN_B; off <<= 1) {
        int tmp = (tid >= off) ? s[tid - off] : 0;
        __syncthreads();
        s[tid] += tmp;
        __syncthreads();
    }
    if (idx < NN) g_off[idx] = s[tid] - v;
    if (tid == SCAN_B - 1) g_bsum[b] = s[tid];
}

__global__ void scan2_kernel()
{
    if (threadIdx.x == 0) {
        int acc = 0;
        for (int b = 0; b < NSCAN; b++) { g_bpre[b] = acc; acc += g_bsum[b]; }
        g_bpre[NSCAN] = acc;
    }
}

__global__ void scan3_kernel()
{
    int idx = blockIdx.x * blockDim.x + threadIdx.x;
    if (idx < NN) {
        int v = g_off[idx] + g_bpre[idx >> 10];
        g_off[idx] = v;
        g_cursor[idx] = v;
    } else if (idx == NN) {
        g_off[NN] = g_bpre[NSCAN];
    }
}

// ---- scatter: CSR srcs + exp(score) + per-(dst,head) sums --------------------
__global__ void scatter_score_kernel(const int* __restrict__ src,
                                     const int* __restrict__ dst,
                                     const int* __restrict__ etype)
{
    int e = blockIdx.x * blockDim.x + threadIdx.x;
    if (e >= EE) return;
    int dv = dst[e];
    int pos = atomicAdd(&g_cursor[dv], 1);
    int sv = src[e], tp = etype[e];
    g_srcs[pos] = sv;
    float4 l = *(const float4*)&g_el[sv * HH];
    float4 r = *(const float4*)&g_er[dv * HH];
    float4 t = *(const float4*)&g_ee[tp * HH];
    float x0 = l.x + r.x + t.x;  x0 = x0 > 0.f ? x0 : SLOPE * x0;
    float x1 = l.y + r.y + t.y;  x1 = x1 > 0.f ? x1 : SLOPE * x1;
    float x2 = l.z + r.z + t.z;  x2 = x2 > 0.f ? x2 : SLOPE * x2;
    float x3 = l.w + r.w + t.w;  x3 = x3 > 0.f ? x3 : SLOPE * x3;
    float p0 = __expf(x0), p1 = __expf(x1), p2 = __expf(x2), p3 = __expf(x3);
    *(float4*)&g_score[(size_t)pos * HH] = make_float4(p0, p1, p2, p3);
    atomicAdd(&g_sum[dv * HH + 0], p0);
    atomicAdd(&g_sum[dv * HH + 1], p1);
    atomicAdd(&g_sum[dv * HH + 2], p2);
    atomicAdd(&g_sum[dv * HH + 3], p3);
}

// ---- out_a: edge-parallel, coalesced writes ----------------------------------
__global__ void out_a_kernel(const int* __restrict__ src,
                             const int* __restrict__ dst,
                             const int* __restrict__ etype,
                             float* __restrict__ out_a)
{
    int e = blockIdx.x * blockDim.x + threadIdx.x;
    if (e >= EE) return;
    int sv = src[e], dv = dst[e], tp = etype[e];
    float4 l = *(const float4*)&g_el[sv * HH];
    float4 r = *(const float4*)&g_er[dv * HH];
    float4 t = *(const float4*)&g_ee[tp * HH];
    float4 s = *(const float4*)&g_sum[dv * HH];
    float x0 = l.x + r.x + t.x;  x0 = x0 > 0.f ? x0 : SLOPE * x0;
    float x1 = l.y + r.y + t.y;  x1 = x1 > 0.f ? x1 : SLOPE * x1;
    float x2 = l.z + r.z + t.z;  x2 = x2 > 0.f ? x2 : SLOPE * x2;
    float x3 = l.w + r.w + t.w;  x3 = x3 > 0.f ? x3 : SLOPE * x3;
    float4 w;
    w.x = __expf(x0) * (1.f / s.x);
    w.y = __expf(x1) * (1.f / s.y);
    w.z = __expf(x2) * (1.f / s.z);
    w.w = __expf(x3) * (1.f / s.w);
    *(float4*)&out_a[(size_t)e * HH] = w;
}

// ---------------- weighted aggregation (rst only) -----------------------------
__global__ void __launch_bounds__(256)
aggregate_kernel(float* __restrict__ out_rst)
{
    const int d   = blockIdx.x;
    const int tid = threadIdx.x;
    const int off = g_off[d];
    const int deg = g_off[d + 1] - off;

    if (deg == 0) { out_rst[(size_t)d * HF + tid] = 0.f; return; }

    __shared__ float Sh[HH];
    __shared__ float w_sh[64 * HH];
    __shared__ int   src_sh[64];

    if (tid < HH) Sh[tid] = 1.f / g_sum[d * HH + tid];
    __syncthreads();

    const int h = tid & 3;
    const int g = tid >> 2;
    const int hh = tid >> 6;
    float acc = 0.f;

    for (int base = 0; base < deg; base += 64) {
        int cnt = min(64, deg - base);
        if (tid < cnt * HH) {
            float p = g_score[(size_t)(off + base) * HH + tid];
            w_sh[tid] = p * Sh[h];
            if (h == 0) src_sh[g] = g_srcs[off + base + g];
        }
        __syncthreads();
#pragma unroll 4
        for (int i = 0; i < cnt; i++) {
            acc += w_sh[i * HH + hh] * __ldg(&g_feat[(size_t)src_sh[i] * HF + tid]);
        }
        __syncthreads();
    }
    out_rst[(size_t)d * HF + tid] = acc;
}

// ---------------- launch ------------------------------------------------------
extern "C" void kernel_launch(void* const* d_in, const int* in_sizes, int n_in,
                              void* d_out, int out_size)
{
    const float* nfeat    = (const float*)d_in[0];
    const float* fc_w     = (const float*)d_in[1];
    const float* fc_e_w   = (const float*)d_in[2];
    const float* attn_l   = (const float*)d_in[3];
    const float* attn_r   = (const float*)d_in[4];
    const float* attn_e   = (const float*)d_in[5];
    const float* edge_emb = (const float*)d_in[6];
    const int*   src      = (const int*)d_in[7];
    const int*   dst      = (const int*)d_in[8];
    const int*   etype    = (const int*)d_in[9];

    float* out_rst = (float*)d_out;
    float* out_a   = (float*)d_out + (size_t)NN * HF;

    float *feat_ptr, *el_ptr, *er_ptr, *sum_ptr;
    int *cnt_ptr;
    cudaGetSymbolAddress((void**)&feat_ptr, g_feat);
    cudaGetSymbolAddress((void**)&el_ptr, g_el);
    cudaGetSymbolAddress((void**)&er_ptr, g_er);
    cudaGetSymbolAddress((void**)&sum_ptr, g_sum);
    cudaGetSymbolAddress((void**)&cnt_ptr, g_cnt);

    static cudaStream_t s1 = nullptr, s2 = nullptr;
    static cudaEvent_t evA = nullptr, evB = nullptr, evC = nullptr,
                       evD = nullptr, evE = nullptr;
    if (!s1) {
        cudaStreamCreateWithFlags(&s1, cudaStreamNonBlocking);
        cudaStreamCreateWithFlags(&s2, cudaStreamNonBlocking);
        cudaEventCreateWithFlags(&evA, cudaEventDisableTiming);
        cudaEventCreateWithFlags(&evB, cudaEventDisableTiming);
        cudaEventCreateWithFlags(&evC, cudaEventDisableTiming);
        cudaEventCreateWithFlags(&evD, cudaEventDisableTiming);
        cudaEventCreateWithFlags(&evE, cudaEventDisableTiming);
        cudaFuncSetAttribute(gemm_mma_kernel,
                             cudaFuncAttributeMaxDynamicSharedMemorySize, GEMM_SMEM);
    }

    // fork from capture-origin stream
    cudaEventRecord(evA, 0);
    cudaStreamWaitEvent(s1, evA, 0);
    cudaStreamWaitEvent(s2, evA, 0);

    // s1: projection path
    cudaMemsetAsync(el_ptr, 0, NN * HH * sizeof(float), s1);
    cudaMemsetAsync(er_ptr, 0, NN * HH * sizeof(float), s1);
    convert_b_kernel<<<(IND * HF / 4 + 255) / 256, 256, 0, s1>>>(fc_w);
    {
        dim3 grid((NN + BM - 1) / BM, HF / BN);
        gemm_mma_kernel<<<grid, 256, GEMM_SMEM, s1>>>(nfeat, feat_ptr, attn_l, attn_r, NN);
    }

    // s2: CSR path (independent of GEMM)
    cudaMemsetAsync(cnt_ptr, 0, (NN + 1) * sizeof(int), s2);
    cudaMemsetAsync(sum_ptr, 0, NN * HH * sizeof(float), s2);
    count_kernel<<<(EE + 255) / 256, 256, 0, s2>>>(dst);
    scan1_kernel<<<NSCAN, SCAN_B, 0, s2>>>();
    scan2_kernel<<<1, 32, 0, s2>>>();
    scan3_kernel<<<(NN + 256) / 256, 256, 0, s2>>>();
    ee_kernel<<<1, 32, 0, s2>>>(edge_emb, fc_e_w, attn_e);

    // join: scatter needs both paths
    cudaEventRecord(evB, s2);
    cudaStreamWaitEvent(s1, evB, 0);
    scatter_score_kernel<<<(EE + 255) / 256, 256, 0, s1>>>(src, dst, etype);

    // fork: out_a (s2) concurrent with aggregate (s1)
    cudaEventRecord(evC, s1);
    cudaStreamWaitEvent(s2, evC, 0);
    out_a_kernel<<<(EE + 255) / 256, 256, 0, s2>>>(src, dst, etype, out_a);
    aggregate_kernel<<<NN, 256, 0, s1>>>(out_rst);

    // join back to origin
    cudaEventRecord(evD, s2);
    cudaStreamWaitEvent(s1, evD, 0);
    cudaEventRecord(evE, s1);
    cudaStreamWaitEvent(0, evE, 0);
}

// round 8
// speedup vs baseline: 2.0534x; 1.2484x over previous
#include <cuda_runtime.h>
#include <cuda_bf16.h>
#include <math.h>
#include <stdint.h>

// Problem constants
#define NN   50000
#define EE   800000
#define IND  256
#define HH   4
#define FF   64
#define HF   256
#define EFD  64
#define NT   8
#define SLOPE 0.2f

// ---------------- scratch ----------------------------------------------------
__device__ float g_feat[NN * HF];
__device__ float g_el[NN * HH];
__device__ float g_er[NN * HH];
__device__ float g_ee[NT * HH];
__device__ float g_sum[NN * HH];
__device__ float g_score[(size_t)EE * HH];    // exp(score), CSR order
__device__ int   g_srcs[EE];                  // src node per CSR slot
__device__ __nv_bfloat16 g_B1[IND * HF];
__device__ __nv_bfloat16 g_B2[IND * HF];
__device__ int   g_cnt[NN + 1];
__device__ int   g_off[NN + 1];
__device__ int   g_cursor[NN];
__device__ int   g_bsum[64];
__device__ int   g_bpre[65];

// ---------------- helpers -----------------------------------------------------
__device__ __forceinline__ uint32_t smem_u32(const void* p) {
    uint32_t a;
    asm("{ .reg .u64 t; cvta.to.shared.u64 t, %1; cvt.u32.u64 %0, t; }"
        : "=r"(a) : "l"(p));
    return a;
}
__device__ __forceinline__ void ldmatrix_x4(uint32_t* r, uint32_t addr) {
    asm volatile("ldmatrix.sync.aligned.m8n8.x4.shared.b16 {%0,%1,%2,%3}, [%4];"
                 : "=r"(r[0]), "=r"(r[1]), "=r"(r[2]), "=r"(r[3]) : "r"(addr));
}
__device__ __forceinline__ void ldmatrix_x4_t(uint32_t* r, uint32_t addr) {
    asm volatile("ldmatrix.sync.aligned.m8n8.x4.trans.shared.b16 {%0,%1,%2,%3}, [%4];"
                 : "=r"(r[0]), "=r"(r[1]), "=r"(r[2]), "=r"(r[3]) : "r"(addr));
}
__device__ __forceinline__ void mma_bf16(float* c, const uint32_t* a,
                                         uint32_t b0, uint32_t b1) {
    asm volatile(
        "mma.sync.aligned.m16n8k16.row.col.f32.bf16.bf16.f32 "
        "{%0,%1,%2,%3}, {%4,%5,%6,%7}, {%8,%9}, {%0,%1,%2,%3};"
        : "+f"(c[0]), "+f"(c[1]), "+f"(c[2]), "+f"(c[3])
        : "r"(a[0]), "r"(a[1]), "r"(a[2]), "r"(a[3]), "r"(b0), "r"(b1));
}
__device__ __forceinline__ uint32_t pack_hi(float a, float b) {
    return ((uint32_t)__bfloat16_as_ushort(__float2bfloat16_rn(b)) << 16) |
           (uint32_t)__bfloat16_as_ushort(__float2bfloat16_rn(a));
}
__device__ __forceinline__ uint32_t pack_lo(float a, float b) {
    float ar = a - __bfloat162float(__float2bfloat16_rn(a));
    float br = b - __bfloat162float(__float2bfloat16_rn(b));
    return ((uint32_t)__bfloat16_as_ushort(__float2bfloat16_rn(br)) << 16) |
           (uint32_t)__bfloat16_as_ushort(__float2bfloat16_rn(ar));
}

// ---------------- B pre-conversion ------------------------------------------
__global__ void convert_b_kernel(const float* __restrict__ Bw)
{
    int i = (blockIdx.x * blockDim.x + threadIdx.x) * 4;
    float4 v = *(const float4*)(Bw + i);
    float f[4] = { v.x, v.y, v.z, v.w };
#pragma unroll
    for (int q = 0; q < 4; q++) {
        __nv_bfloat16 h = __float2bfloat16_rn(f[q]);
        g_B1[i + q] = h;
        g_B2[i + q] = __float2bfloat16_rn(f[q] - __bfloat162float(h));
    }
}

// ---------------- bf16-split GEMM, double-buffered smem, fused el/er ---------
#define BM 128
#define BN 128
#define BK 32
#define AST 40
#define BST 136
#define STG_A1 0
#define STG_A2 10240
#define STG_B1 20480
#define STG_B2 29184
#define STG_SZ 37888
#define GEMM_SMEM (2 * STG_SZ)

__global__ void __launch_bounds__(256, 2)
gemm_mma_kernel(const float* __restrict__ A, float* __restrict__ C,
                const float* __restrict__ attn_l, const float* __restrict__ attn_r,
                int M)
{
    extern __shared__ __align__(16) char dynsm[];

    const int tid  = threadIdx.x;
    const int lane = tid & 31;
    const int wid  = tid >> 5;
    const int m0 = blockIdx.x * BM;
    const int n0 = blockIdx.y * BN;

    const int wm = (wid & 1) * 64;
    const int wn = (wid >> 1) * 32;

    float acc[4][4][4];
#pragma unroll
    for (int i = 0; i < 4; i++)
#pragma unroll
        for (int j = 0; j < 4; j++)
#pragma unroll
            for (int r = 0; r < 4; r++) acc[i][j][r] = 0.f;

    const int a_row  = tid >> 1;
    const int a_colb = (tid & 1) * 16;
    const int a_gr   = m0 + a_row;
    const int b_kr  = tid >> 3;
    const int b_nb  = (tid & 7) * 16;

    const int mat  = lane >> 3;
    const int l8   = lane & 7;
    const int a_mrow = (mat & 1) * 8 + l8;
    const int a_koff = (mat >> 1) * 8;
    const int b_krow = (mat & 1) * 8 + l8;
    const int b_noff = (mat >> 1) * 8;

    const uint32_t sm0 = smem_u32(dynsm);

    float4 va[4];
    uint4 vbh[2], vbl[2];
    {
        if (a_gr < M) {
            const float4* p = (const float4*)(A + (size_t)a_gr * IND + a_colb);
#pragma unroll
            for (int q = 0; q < 4; q++) va[q] = p[q];
        } else {
#pragma unroll
            for (int q = 0; q < 4; q++) va[q] = make_float4(0, 0, 0, 0);
        }
        const uint4* p1 = (const uint4*)(g_B1 + (size_t)b_kr * HF + n0 + b_nb);
        const uint4* p2 = (const uint4*)(g_B2 + (size_t)b_kr * HF + n0 + b_nb);
        vbh[0] = p1[0]; vbh[1] = p1[1];
        vbl[0] = p2[0]; vbl[1] = p2[1];
    }

    for (int c = 0; c < IND / BK; c++) {
        char* stg = dynsm + (c & 1) * STG_SZ;
        {
            uint32_t hi[8], lo[8];
#pragma unroll
            for (int q = 0; q < 4; q++) {
                hi[2 * q]     = pack_hi(va[q].x, va[q].y);
                hi[2 * q + 1] = pack_hi(va[q].z, va[q].w);
                lo[2 * q]     = pack_lo(va[q].x, va[q].y);
                lo[2 * q + 1] = pack_lo(va[q].z, va[q].w);
            }
            char* d1 = stg + STG_A1 + (a_row * AST + a_colb) * 2;
            char* d2 = stg + STG_A2 + (a_row * AST + a_colb) * 2;
            ((uint4*)d1)[0] = make_uint4(hi[0], hi[1], hi[2], hi[3]);
            ((uint4*)d1)[1] = make_uint4(hi[4], hi[5], hi[6], hi[7]);
            ((uint4*)d2)[0] = make_uint4(lo[0], lo[1], lo[2], lo[3]);
            ((uint4*)d2)[1] = make_uint4(lo[4], lo[5], lo[6], lo[7]);
            char* e1 = stg + STG_B1 + (b_kr * BST + b_nb) * 2;
            char* e2 = stg + STG_B2 + (b_kr * BST + b_nb) * 2;
            ((uint4*)e1)[0] = vbh[0];
            ((uint4*)e1)[1] = vbh[1];
            ((uint4*)e2)[0] = vbl[0];
            ((uint4*)e2)[1] = vbl[1];
        }
        __syncthreads();

        if (c + 1 < IND / BK) {
            const int k0 = (c + 1) * BK;
            if (a_gr < M) {
                const float4* p = (const float4*)(A + (size_t)a_gr * IND + k0 + a_colb);
#pragma unroll
                for (int q = 0; q < 4; q++) va[q] = p[q];
            } else {
#pragma unroll
                for (int q = 0; q < 4; q++) va[q] = make_float4(0, 0, 0, 0);
            }
            const uint4* p1 = (const uint4*)(g_B1 + (size_t)(k0 + b_kr) * HF + n0 + b_nb);
            const uint4* p2 = (const uint4*)(g_B2 + (size_t)(k0 + b_kr) * HF + n0 + b_nb);
            vbh[0] = p1[0]; vbh[1] = p1[1];
            vbl[0] = p2[0]; vbl[1] = p2[1];
        }

        const uint32_t sa1 = sm0 + (c & 1) * STG_SZ + STG_A1;
        const uint32_t sa2 = sm0 + (c & 1) * STG_SZ + STG_A2;
        const uint32_t sb1 = sm0 + (c & 1) * STG_SZ + STG_B1;
        const uint32_t sb2 = sm0 + (c & 1) * STG_SZ + STG_B2;

#pragma unroll
        for (int kk = 0; kk < 2; kk++) {
            uint32_t a1[4][4], a2[4][4], b1[2][4], b2[2][4];
#pragma unroll
            for (int i = 0; i < 4; i++) {
                uint32_t off = ((wm + i * 16 + a_mrow) * AST + kk * 16 + a_koff) * 2;
                ldmatrix_x4(a1[i], sa1 + off);
                ldmatrix_x4(a2[i], sa2 + off);
            }
#pragma unroll
            for (int j2 = 0; j2 < 2; j2++) {
                uint32_t off = ((kk * 16 + b_krow) * BST + wn + j2 * 16 + b_noff) * 2;
                ldmatrix_x4_t(b1[j2], sb1 + off);
                ldmatrix_x4_t(b2[j2], sb2 + off);
            }
#pragma unroll
            for (int i = 0; i < 4; i++) {
#pragma unroll
                for (int j2 = 0; j2 < 2; j2++) {
                    mma_bf16(acc[i][2 * j2],     a1[i], b1[j2][0], b1[j2][1]);
                    mma_bf16(acc[i][2 * j2],     a1[i], b2[j2][0], b2[j2][1]);
                    mma_bf16(acc[i][2 * j2],     a2[i], b1[j2][0], b1[j2][1]);
                    mma_bf16(acc[i][2 * j2 + 1], a1[i], b1[j2][2], b1[j2][3]);
                    mma_bf16(acc[i][2 * j2 + 1], a1[i], b2[j2][2], b2[j2][3]);
                    mma_bf16(acc[i][2 * j2 + 1], a2[i], b1[j2][2], b1[j2][3]);
                }
            }
        }
    }

    // ---- epilogue: store C + fused el/er
    const int crow = lane >> 2;
    const int ccol = (lane & 3) * 2;

    float al[4][2], ar[4][2];
#pragma unroll
    for (int j = 0; j < 4; j++) {
        int c = n0 + wn + j * 8 + ccol;
        al[j][0] = attn_l[c];     al[j][1] = attn_l[c + 1];
        ar[j][0] = attn_r[c];     ar[j][1] = attn_r[c + 1];
    }
    const int head = (n0 + wn) >> 6;

#pragma unroll
    for (int i = 0; i < 4; i++) {
        int r0 = m0 + wm + i * 16 + crow;
        float pl0 = 0.f, pr0 = 0.f, pl1 = 0.f, pr1 = 0.f;
#pragma unroll
        for (int j = 0; j < 4; j++) {
            int c = n0 + wn + j * 8 + ccol;
            if (r0 < M)
                *(float2*)(C + (size_t)r0 * HF + c) = make_float2(acc[i][j][0], acc[i][j][1]);
            if (r0 + 8 < M)
                *(float2*)(C + (size_t)(r0 + 8) * HF + c) = make_float2(acc[i][j][2], acc[i][j][3]);
            pl0 += acc[i][j][0] * al[j][0] + acc[i][j][1] * al[j][1];
            pr0 += acc[i][j][0] * ar[j][0] + acc[i][j][1] * ar[j][1];
            pl1 += acc[i][j][2] * al[j][0] + acc[i][j][3] * al[j][1];
            pr1 += acc[i][j][2] * ar[j][0] + acc[i][j][3] * ar[j][1];
        }
#pragma unroll
        for (int o = 1; o <= 2; o <<= 1) {
            pl0 += __shfl_xor_sync(0xffffffffu, pl0, o);
            pr0 += __shfl_xor_sync(0xffffffffu, pr0, o);
            pl1 += __shfl_xor_sync(0xffffffffu, pl1, o);
            pr1 += __shfl_xor_sync(0xffffffffu, pr1, o);
        }
        if ((lane & 3) == 0) {
            if (r0 < M) {
                atomicAdd(&g_el[r0 * HH + head], pl0);
                atomicAdd(&g_er[r0 * HH + head], pr0);
            }
            if (r0 + 8 < M) {
                atomicAdd(&g_el[(r0 + 8) * HH + head], pl1);
                atomicAdd(&g_er[(r0 + 8) * HH + head], pr1);
            }
        }
    }
}

// ---------------- ee per etype ------------------------------------------------
__global__ void ee_kernel(const float* __restrict__ edge_emb,
                          const float* __restrict__ fc_e_w,
                          const float* __restrict__ attn_e)
{
    int t = threadIdx.x;
    if (t >= NT * HH) return;
    int tt = t >> 2, h = t & 3;
    float sum = 0.f;
    for (int e = 0; e < EFD; e++) {
        float ef = 0.f;
#pragma unroll 8
        for (int k = 0; k < EFD; k++)
            ef += edge_emb[tt * EFD + k] * fc_e_w[k * (HH * EFD) + h * EFD + e];
        sum += ef * attn_e[h * EFD + e];
    }
    g_ee[tt * HH + h] = sum;
}

// ---------------- CSR build ---------------------------------------------------
__global__ void count_kernel(const int* __restrict__ dst)
{
    int e = blockIdx.x * blockDim.x + threadIdx.x;
    if (e < EE) atomicAdd(&g_cnt[dst[e]], 1);
}

#define SCAN_B 1024
#define NSCAN ((NN + SCAN_B - 1) / SCAN_B)

__global__ void scan1_kernel()
{
    __shared__ int s[SCAN_B];
    int b = blockIdx.x, tid = threadIdx.x;
    int idx = b * SCAN_B + tid;
    int v = (idx < NN) ? g_cnt[idx] : 0;
    s[tid] = v;
    __syncthreads();
    for (int off = 1; off < SCAN_B; off <<= 1) {
        int tmp = (tid >= off) ? s[tid - off] : 0;
        __syncthreads();
        s[tid] += tmp;
        __syncthreads();
    }
    if (idx < NN) g_off[idx] = s[tid] - v;
    if (tid == SCAN_B - 1) g_bsum[b] = s[tid];
}

__global__ void scan2_kernel()
{
    if (threadIdx.x == 0) {
        int acc = 0;
        for (int b = 0; b < NSCAN; b++) { g_bpre[b] = acc; acc += g_bsum[b]; }
        g_bpre[NSCAN] = acc;
    }
}

__global__ void scan3_kernel()
{
    int idx = blockIdx.x * blockDim.x + threadIdx.x;
    if (idx < NN) {
        int v = g_off[idx] + g_bpre[idx >> 10];
        g_off[idx] = v;
        g_cursor[idx] = v;
    } else if (idx == NN) {
        g_off[NN] = g_bpre[NSCAN];
    }
}

// ---- scatter: CSR srcs + exp(score) + per-(dst,head) sums --------------------
__global__ void scatter_score_kernel(const int* __restrict__ src,
                                     const int* __restrict__ dst,
                                     const int* __restrict__ etype)
{
    int e = blockIdx.x * blockDim.x + threadIdx.x;
    if (e >= EE) return;
    int dv = dst[e];
    int pos = atomicAdd(&g_cursor[dv], 1);
    int sv = src[e], tp = etype[e];
    g_srcs[pos] = sv;
    float4 l = *(const float4*)&g_el[sv * HH];
    float4 r = *(const float4*)&g_er[dv * HH];
    float4 t = *(const float4*)&g_ee[tp * HH];
    float x0 = l.x + r.x + t.x;  x0 = x0 > 0.f ? x0 : SLOPE * x0;
    float x1 = l.y + r.y + t.y;  x1 = x1 > 0.f ? x1 : SLOPE * x1;
    float x2 = l.z + r.z + t.z;  x2 = x2 > 0.f ? x2 : SLOPE * x2;
    float x3 = l.w + r.w + t.w;  x3 = x3 > 0.f ? x3 : SLOPE * x3;
    float p0 = __expf(x0), p1 = __expf(x1), p2 = __expf(x2), p3 = __expf(x3);
    *(float4*)&g_score[(size_t)pos * HH] = make_float4(p0, p1, p2, p3);
    atomicAdd(&g_sum[dv * HH + 0], p0);
    atomicAdd(&g_sum[dv * HH + 1], p1);
    atomicAdd(&g_sum[dv * HH + 2], p2);
    atomicAdd(&g_sum[dv * HH + 3], p3);
}

// ---- out_a: edge-parallel, coalesced writes ----------------------------------
__global__ void out_a_kernel(const int* __restrict__ src,
                             const int* __restrict__ dst,
                             const int* __restrict__ etype,
                             float* __restrict__ out_a)
{
    int e = blockIdx.x * blockDim.x + threadIdx.x;
    if (e >= EE) return;
    int sv = src[e], dv = dst[e], tp = etype[e];
    float4 l = *(const float4*)&g_el[sv * HH];
    float4 r = *(const float4*)&g_er[dv * HH];
    float4 t = *(const float4*)&g_ee[tp * HH];
    float4 s = *(const float4*)&g_sum[dv * HH];
    float x0 = l.x + r.x + t.x;  x0 = x0 > 0.f ? x0 : SLOPE * x0;
    float x1 = l.y + r.y + t.y;  x1 = x1 > 0.f ? x1 : SLOPE * x1;
    float x2 = l.z + r.z + t.z;  x2 = x2 > 0.f ? x2 : SLOPE * x2;
    float x3 = l.w + r.w + t.w;  x3 = x3 > 0.f ? x3 : SLOPE * x3;
    float4 w;
    w.x = __expf(x0) * (1.f / s.x);
    w.y = __expf(x1) * (1.f / s.y);
    w.z = __expf(x2) * (1.f / s.z);
    w.w = __expf(x3) * (1.f / s.w);
    *(float4*)&out_a[(size_t)e * HH] = w;
}

// ---------------- warp-per-dst weighted aggregation ---------------------------
__global__ void __launch_bounds__(256)
aggregate_kernel(float* __restrict__ out_rst)
{
    const int d    = blockIdx.x * 8 + (threadIdx.x >> 5);
    const int lane = threadIdx.x & 31;
    if (d >= NN) return;

    const int off = g_off[d];
    const int deg = g_off[d + 1] - off;
    const int hh  = lane >> 3;            // head owned by this lane's columns

    float4 a0 = make_float4(0.f, 0.f, 0.f, 0.f);
    float4 a1 = make_float4(0.f, 0.f, 0.f, 0.f);

    if (deg > 0) {
        const float rs = 1.f / g_sum[d * HH + hh];
        int i = 0;
        for (; i + 2 <= deg; i += 2) {
            int   sv0 = __ldg(&g_srcs[off + i]);
            int   sv1 = __ldg(&g_srcs[off + i + 1]);
            float p0  = __ldg(&g_score[(size_t)(off + i) * HH + hh]);
            float p1  = __ldg(&g_score[(size_t)(off + i + 1) * HH + hh]);
            const float4* f0 = (const float4*)(g_feat + (size_t)sv0 * HF + lane * 8);
            const float4* f1 = (const float4*)(g_feat + (size_t)sv1 * HF + lane * 8);
            float4 v00 = f0[0], v01 = f0[1];
            float4 v10 = f1[0], v11 = f1[1];
            float w0 = p0 * rs, w1 = p1 * rs;
            a0.x += w0 * v00.x; a0.y += w0 * v00.y; a0.z += w0 * v00.z; a0.w += w0 * v00.w;
            a1.x += w0 * v01.x; a1.y += w0 * v01.y; a1.z += w0 * v01.z; a1.w += w0 * v01.w;
            a0.x += w1 * v10.x; a0.y += w1 * v10.y; a0.z += w1 * v10.z; a0.w += w1 * v10.w;
            a1.x += w1 * v11.x; a1.y += w1 * v11.y; a1.z += w1 * v11.z; a1.w += w1 * v11.w;
        }
        if (i < deg) {
            int   sv = __ldg(&g_srcs[off + i]);
            float p  = __ldg(&g_score[(size_t)(off + i) * HH + hh]);
            const float4* f = (const float4*)(g_feat + (size_t)sv * HF + lane * 8);
            float4 v0 = f[0], v1 = f[1];
            float w = p * rs;
            a0.x += w * v0.x; a0.y += w * v0.y; a0.z += w * v0.z; a0.w += w * v0.w;
            a1.x += w * v1.x; a1.y += w * v1.y; a1.z += w * v1.z; a1.w += w * v1.w;
        }
    }

    float4* op = (float4*)(out_rst + (size_t)d * HF + lane * 8);
    op[0] = a0;
    op[1] = a1;
}

// ---------------- launch ------------------------------------------------------
extern "C" void kernel_launch(void* const* d_in, const int* in_sizes, int n_in,
                              void* d_out, int out_size)
{
    const float* nfeat    = (const float*)d_in[0];
    const float* fc_w     = (const float*)d_in[1];
    const float* fc_e_w   = (const float*)d_in[2];
    const float* attn_l   = (const float*)d_in[3];
    const float* attn_r   = (const float*)d_in[4];
    const float* attn_e   = (const float*)d_in[5];
    const float* edge_emb = (const float*)d_in[6];
    const int*   src      = (const int*)d_in[7];
    const int*   dst      = (const int*)d_in[8];
    const int*   etype    = (const int*)d_in[9];

    float* out_rst = (float*)d_out;
    float* out_a   = (float*)d_out + (size_t)NN * HF;

    float *feat_ptr, *el_ptr, *er_ptr, *sum_ptr;
    int *cnt_ptr;
    cudaGetSymbolAddress((void**)&feat_ptr, g_feat);
    cudaGetSymbolAddress((void**)&el_ptr, g_el);
    cudaGetSymbolAddress((void**)&er_ptr, g_er);
    cudaGetSymbolAddress((void**)&sum_ptr, g_sum);
    cudaGetSymbolAddress((void**)&cnt_ptr, g_cnt);

    static cudaStream_t s1 = nullptr, s2 = nullptr;
    static cudaEvent_t evA = nullptr, evB = nullptr, evC = nullptr,
                       evD = nullptr, evE = nullptr;
    if (!s1) {
        cudaStreamCreateWithFlags(&s1, cudaStreamNonBlocking);
        cudaStreamCreateWithFlags(&s2, cudaStreamNonBlocking);
        cudaEventCreateWithFlags(&evA, cudaEventDisableTiming);
        cudaEventCreateWithFlags(&evB, cudaEventDisableTiming);
        cudaEventCreateWithFlags(&evC, cudaEventDisableTiming);
        cudaEventCreateWithFlags(&evD, cudaEventDisableTiming);
        cudaEventCreateWithFlags(&evE, cudaEventDisableTiming);
        cudaFuncSetAttribute(gemm_mma_kernel,
                             cudaFuncAttributeMaxDynamicSharedMemorySize, GEMM_SMEM);
    }

    // fork from capture-origin stream
    cudaEventRecord(evA, 0);
    cudaStreamWaitEvent(s1, evA, 0);
    cudaStreamWaitEvent(s2, evA, 0);

    // s1: projection path
    cudaMemsetAsync(el_ptr, 0, NN * HH * sizeof(float), s1);
    cudaMemsetAsync(er_ptr, 0, NN * HH * sizeof(float), s1);
    convert_b_kernel<<<(IND * HF / 4 + 255) / 256, 256, 0, s1>>>(fc_w);
    {
        dim3 grid((NN + BM - 1) / BM, HF / BN);
        gemm_mma_kernel<<<grid, 256, GEMM_SMEM, s1>>>(nfeat, feat_ptr, attn_l, attn_r, NN);
    }

    // s2: CSR path (independent of GEMM)
    cudaMemsetAsync(cnt_ptr, 0, (NN + 1) * sizeof(int), s2);
    cudaMemsetAsync(sum_ptr, 0, NN * HH * sizeof(float), s2);
    count_kernel<<<(EE + 255) / 256, 256, 0, s2>>>(dst);
    scan1_kernel<<<NSCAN, SCAN_B, 0, s2>>>();
    scan2_kernel<<<1, 32, 0, s2>>>();
    scan3_kernel<<<(NN + 256) / 256, 256, 0, s2>>>();
    ee_kernel<<<1, 32, 0, s2>>>(edge_emb, fc_e_w, attn_e);

    // join: scatter needs both paths
    cudaEventRecord(evB, s2);
    cudaStreamWaitEvent(s1, evB, 0);
    scatter_score_kernel<<<(EE + 255) / 256, 256, 0, s1>>>(src, dst, etype);

    // fork: out_a (s2) concurrent with aggregate (s1)
    cudaEventRecord(evC, s1);
    cudaStreamWaitEvent(s2, evC, 0);
    out_a_kernel<<<(EE + 255) / 256, 256, 0, s2>>>(src, dst, etype, out_a);
    aggregate_kernel<<<(NN + 7) / 8, 256, 0, s1>>>(out_rst);

    // join back to origin
    cudaEventRecord(evD, s2);
    cudaStreamWaitEvent(s1, evD, 0);
    cudaEventRecord(evE, s1);
    cudaStreamWaitEvent(0, evE, 0);
}